// round 13
// baseline (speedup 1.0000x reference)
#include <cuda_runtime.h>
#include <math.h>

#define Gn 128
typedef unsigned long long U64;

static const long long O_XOUT=0LL, O_Z=33554432LL, O_ZHAT=50331648LL, O_SURP=67108864LL,
 O_KC=67371008LL, O_VP=84148224LL, O_GATE=100925440LL, O_QN=101187584LL,
 O_VC=117964800LL, O_WN=134742016LL, O_S4=135004160LL;

__device__ __forceinline__ void f2fma(U64& d, U64 a, U64 b){
    asm("fma.rn.f32x2 %0, %1, %2, %0;" : "+l"(d) : "l"(a), "l"(b));
}
__device__ __forceinline__ void f2add(U64& d, U64 a){
    asm("add.rn.f32x2 %0, %0, %1;" : "+l"(d) : "l"(a));
}
__device__ __forceinline__ U64 dup2(float a){
    U64 r; asm("mov.b64 %0, {%1, %1};" : "=l"(r) : "f"(a)); return r;
}
__device__ __forceinline__ float4 pk4(U64 p0, U64 p1){
    float4 v;
    asm("mov.b64 {%0, %1}, %2;" : "=f"(v.x), "=f"(v.y) : "l"(p0));
    asm("mov.b64 {%0, %1}, %2;" : "=f"(v.z), "=f"(v.w) : "l"(p1));
    return v;
}
__device__ __forceinline__ float4 pksel(const U64* c, int flag){
    U64 p0 = flag ? c[2] : c[0];
    U64 p1 = flag ? c[3] : c[1];
    return pk4(p0, p1);
}
__device__ __forceinline__ void cpa16(float* dst, const float* src){
    unsigned d = (unsigned)__cvta_generic_to_shared(dst);
    asm volatile("cp.async.ca.shared.global [%0], [%1], 16;" :: "r"(d), "l"(src) : "memory");
}
__device__ __forceinline__ void cpa4(float* dst, const float* src){
    unsigned d = (unsigned)__cvta_generic_to_shared(dst);
    asm volatile("cp.async.ca.shared.global [%0], [%1], 4;" :: "r"(d), "l"(src) : "memory");
}
__device__ __forceinline__ void cpcommit(){ asm volatile("cp.async.commit_group;" ::: "memory"); }
__device__ __forceinline__ void cpwait0(){ asm volatile("cp.async.wait_group 0;" ::: "memory"); }
__device__ __forceinline__ void fz2(U64* c){
#pragma unroll
    for (int i=0;i<16;i++) c[i]=0ULL;
}
__device__ __forceinline__ void redK2(U64* c){
#pragma unroll
    for (int i=0;i<16;i++) f2add(c[i], __shfl_xor_sync(0xffffffffu, c[i], 16));
}
__device__ __forceinline__ void redK4(U64* c){
#pragma unroll
    for (int i=0;i<16;i++){
        f2add(c[i], __shfl_xor_sync(0xffffffffu, c[i], 8));
        f2add(c[i], __shfl_xor_sync(0xffffffffu, c[i], 16));
    }
}

// ---- inner loops: warp = 4 tokens (ty); lanes split K (interleaved) ----
__device__ __forceinline__ void innU64(const float* As, int kbase, const float* wb, int rbase,
                                       U64 c2[][4], int ty, int tx8){
    float4 a4[4];
#pragma unroll
    for (int tt=0;tt<4;tt++) a4[tt] = *(const float4*)&As[(ty*4+tt)*132 + kbase];
#pragma unroll
    for (int r=0;r<4;r++){
        ulonglong2 w0 = *(const ulonglong2*)&wb[(rbase+r)*64 + tx8*4];
        ulonglong2 w1 = *(const ulonglong2*)&wb[(rbase+r)*64 + 32 + tx8*4];
#pragma unroll
        for (int tt=0;tt<4;tt++){
            U64 a = dup2(((const float*)&a4[tt])[r]);
            f2fma(c2[tt][0],a,w0.x); f2fma(c2[tt][1],a,w0.y);
            f2fma(c2[tt][2],a,w1.x); f2fma(c2[tt][3],a,w1.y);
        }
    }
}
__device__ __forceinline__ void innU128(const float* As, int kbase, const float* wb, int rbase,
                                        U64 c2[][4], int ty, int tx){
#pragma unroll
    for (int rp=0;rp<2;rp++){
        float2 a2[4];
#pragma unroll
        for (int tt=0;tt<4;tt++) a2[tt] = *(const float2*)&As[(ty*4+tt)*132 + kbase + rp*2];
#pragma unroll
        for (int rr=0;rr<2;rr++){
            int r = rp*2+rr;
            ulonglong2 w0 = *(const ulonglong2*)&wb[(rbase+r)*128 + tx*4];
            ulonglong2 w1 = *(const ulonglong2*)&wb[(rbase+r)*128 + 64 + tx*4];
#pragma unroll
            for (int tt=0;tt<4;tt++){
                U64 a = dup2(rr ? a2[tt].y : a2[tt].x);
                f2fma(c2[tt][0],a,w0.x); f2fma(c2[tt][1],a,w0.y);
                f2fma(c2[tt][2],a,w1.x); f2fma(c2[tt][3],a,w1.y);
            }
        }
    }
}

// ---- GEMM drivers: double-buffered cp.async, staging by threads 0-255 ----
__device__ __forceinline__ void g64(const float* As, const float* __restrict__ W, long wst, int K,
                                    float* wsm, U64 c2[][4], int ty, int kh2, int tx8, int tid){
    int nc = K>>4;
    bool st = tid < 256;
    int rr = tid>>4, c4 = (tid&15)*4;
    if (st) cpa16(&wsm[rr*64+c4], &W[(size_t)rr*wst + c4]);
    cpcommit();
    for (int c=0;c<nc;c++){
        cpwait0(); __syncthreads();
        if (c+1<nc){
            if (st) cpa16(&wsm[((c+1)&1)*1024 + rr*64+c4], &W[(size_t)((c+1)*16+rr)*wst + c4]);
            cpcommit();
        }
        innU64(As, c*16 + kh2*4, wsm + (c&1)*1024, kh2*4, c2, ty, tx8);
    }
    __syncthreads();
}
__device__ __forceinline__ void g64T(const float* As, const float* __restrict__ S, int slots,
                                     float* wsm, U64 c2[][4], int ty, int kh2, int tx8, int tid){
    int s = tid&63, q = (tid>>6)&3;
    bool st = tid < 256;
    for (int c=0;c<4;c++){
        float4 v = make_float4(0.f,0.f,0.f,0.f);
        if (st && s < slots) v = *(const float4*)&S[s*64 + c*16 + q*4];
        __syncthreads();
        if (st){
            wsm[(q*4+0)*64+s]=v.x; wsm[(q*4+1)*64+s]=v.y;
            wsm[(q*4+2)*64+s]=v.z; wsm[(q*4+3)*64+s]=v.w;
        }
        __syncthreads();
        innU64(As, c*16 + kh2*4, wsm, kh2*4, c2, ty, tx8);
    }
    __syncthreads();
}
template<bool UA>
__device__ __forceinline__ void g128(const float* As, const float* __restrict__ W, long wst, int K,
                                     float* wsm, U64 c2[][4], int ty, int kh, int tx, int tid){
    int nc = K>>3;
    bool st = tid < 256;
    int rr8 = tid>>5, c48 = (tid&31)*4;
#define STAGE128(cc, buf) do { \
    if (st){ \
        if (UA){ \
            for (int j=0;j<4;j++){ int flat=tid+256*j; int r_=flat>>7, col_=flat&127; \
                cpa4(&(buf)[r_*128+col_], &W[(size_t)((cc)*8 + r_)*wst + col_]); } \
        } else { \
            cpa16(&(buf)[rr8*128+c48], &W[(size_t)((cc)*8 + rr8)*wst + c48]); \
        } \
    } \
    cpcommit(); } while(0)
    STAGE128(0, wsm);
    for (int c=0;c<nc;c++){
        cpwait0(); __syncthreads();
        if (c+1<nc) STAGE128(c+1, wsm + ((c+1)&1)*1024);
        innU128(As, c*8 + kh*4, wsm + (c&1)*1024, kh*4, c2, ty, tx);
    }
    __syncthreads();
#undef STAGE128
}

// ---- epilogues ----
__device__ __forceinline__ void eps64(U64 c2[][4], float* buf, const float* bias,
                                      int ty, int kh2, int tx8){
    if (kh2 >= 2) return;
    int col = kh2*32 + tx8*4;
    float4 bv = bias ? *(const float4*)&bias[col] : make_float4(0.f,0.f,0.f,0.f);
#pragma unroll
    for (int tt=0;tt<4;tt++){
        float4 v = pksel(c2[tt], kh2);
        v.x+=bv.x; v.y+=bv.y; v.z+=bv.z; v.w+=bv.w;
        *(float4*)&buf[(ty*4+tt)*132 + col] = v;
    }
}

template <int SLOTS>
__device__ __forceinline__ void softmax8(float* buf, int tok, int j8){
    const int nS = SLOTS/8;
    float l[nS]; float m = -1e30f;
#pragma unroll
    for (int i=0;i<nS;i++){ l[i] = buf[tok*132 + j8*nS + i]*0.125f; m = fmaxf(m, l[i]); }
    m = fmaxf(m, __shfl_xor_sync(0xffffffffu, m, 1));
    m = fmaxf(m, __shfl_xor_sync(0xffffffffu, m, 2));
    m = fmaxf(m, __shfl_xor_sync(0xffffffffu, m, 4));
    float s = 0.f;
#pragma unroll
    for (int i=0;i<nS;i++){ l[i]=expf(l[i]-m); s+=l[i]; }
    s += __shfl_xor_sync(0xffffffffu, s, 1);
    s += __shfl_xor_sync(0xffffffffu, s, 2);
    s += __shfl_xor_sync(0xffffffffu, s, 4);
    float inv = 1.f/s;
#pragma unroll
    for (int i=0;i<nS;i++) buf[tok*132 + j8*nS + i] = l[i]*inv;
}

__global__ void __launch_bounds__(512, 2)
ccg_kernel(
    const float* __restrict__ x_col, const float* __restrict__ pm_state,
    const float* __restrict__ em_state, const float* __restrict__ z_hat_prev,
    const float* __restrict__ ffn_norm_w, const float* __restrict__ ffn_norm_b,
    const float* __restrict__ ffn_up_w, const float* __restrict__ ffn_up_b,
    const float* __restrict__ ffn_down_w, const float* __restrict__ ffn_down_b,
    const float* __restrict__ pm_up_w, const float* __restrict__ pm_up_b,
    const float* __restrict__ pm_down_w, const float* __restrict__ pm_down_b,
    const float* __restrict__ em_up_w, const float* __restrict__ em_up_b,
    const float* __restrict__ em_down_w, const float* __restrict__ em_down_b,
    const float* __restrict__ post_w, const float* __restrict__ post_b,
    const float* __restrict__ enc_w, const float* __restrict__ enc_b,
    const float* __restrict__ pred_w, const float* __restrict__ pred_b,
    const float* __restrict__ gain_w, const float* __restrict__ gain_b,
    float* __restrict__ out)
{
    extern __shared__ float smf[];
    float* xs  = smf;               // 64 x 132 residual
    float* hs  = xs + 64*132;       // 64 x 132 logits/z/gain/gelu/post-k
    float* bC  = hs + 64*132;       // 64 x 132 q/apply/delta/h
    float* wsm = bC + 64*132;       // 2 x 1024 weight staging

    const int tid = threadIdx.x;
    const int lane = tid & 31, ty = tid >> 5;        // warp = 4 tokens
    const int kh = lane >> 4, tx = lane & 15;
    const int kh2 = lane >> 3, tx8 = lane & 7;
    const int tok = tid >> 3, j8 = tid & 7;          // 8 threads / token
    const int g = blockIdx.y, t0 = blockIdx.x*64;
    const int bs = t0 >> 9, bidx = g >> 4;

    U64 c2[4][4];

#pragma unroll
    for (int jj=0;jj<4;jj++){
        int flat = tid + 512*jj, r = flat>>5, c4 = flat&31;
        *(float4*)&xs[r*132 + c4*4] =
            *(const float4*)&x_col[((size_t)(t0+r)*Gn + g)*128 + c4*4];
    }

    // ===== pm stage =====
    fz2(&c2[0][0]);
    g64(xs, pm_up_w + (size_t)g*8192, 64, 128, wsm, c2, ty, kh2, tx8, tid);
    redK4(&c2[0][0]);
    eps64(c2, bC, pm_up_b + g*64, ty, kh2, tx8);

    const float* Spm = pm_state + (size_t)((bs*8 + bidx)*16)*64;
    fz2(&c2[0][0]);
    g64T(bC, Spm, 16, wsm, c2, ty, kh2, tx8, tid);
    redK4(&c2[0][0]);
    eps64(c2, hs, (const float*)0, ty, kh2, tx8);
    __syncthreads();
    softmax8<16>(hs, tok, j8);
    __syncthreads();

    fz2(&c2[0][0]);
    g64(hs, Spm, 64, 16, wsm, c2, ty, kh2, tx8, tid);
    redK4(&c2[0][0]);
    eps64(c2, bC, (const float*)0, ty, kh2, tx8);

    fz2(&c2[0][0]);
    g128<false>(bC, pm_down_w + (size_t)g*8192, 128, 64, wsm, c2, ty, kh, tx, tid);
    redK2(&c2[0][0]);
    {   int col = kh*64 + tx*4;
        float4 bv = *(const float4*)&pm_down_b[g*128 + col];
#pragma unroll
        for (int tt=0;tt<4;tt++){
            float* p = &xs[(ty*4+tt)*132 + col];
            float4 x = *(float4*)p; float4 v = pksel(c2[tt], kh);
            x.x+=v.x+bv.x; x.y+=v.y+bv.y; x.z+=v.z+bv.z; x.w+=v.w+bv.w;
            *(float4*)p = x;
        }
    }

    // ===== em stage =====
    fz2(&c2[0][0]);
    g64(xs, em_up_w + (size_t)g*8192, 64, 128, wsm, c2, ty, kh2, tx8, tid);
    redK4(&c2[0][0]);
    eps64(c2, bC, em_up_b + g*64, ty, kh2, tx8);

    const float* Sem = em_state + (size_t)((bs*8 + bidx)*64)*64;
    fz2(&c2[0][0]);
    g64T(bC, Sem, 64, wsm, c2, ty, kh2, tx8, tid);
    redK4(&c2[0][0]);
    eps64(c2, hs, (const float*)0, ty, kh2, tx8);
    __syncthreads();
    softmax8<64>(hs, tok, j8);
    __syncthreads();

    fz2(&c2[0][0]);
    g64(hs, Sem, 64, 64, wsm, c2, ty, kh2, tx8, tid);
    redK4(&c2[0][0]);
    eps64(c2, bC, (const float*)0, ty, kh2, tx8);

    fz2(&c2[0][0]);
    g128<false>(bC, em_down_w + (size_t)g*8192, 128, 64, wsm, c2, ty, kh, tx, tid);
    redK2(&c2[0][0]);
    {   int col = kh*64 + tx*4;
        float4 bv = *(const float4*)&em_down_b[g*128 + col];
#pragma unroll
        for (int tt=0;tt<4;tt++){
            float* p = &xs[(ty*4+tt)*132 + col];
            float4 x = *(float4*)p; float4 v = pksel(c2[tt], kh);
            x.x+=v.x+bv.x; x.y+=v.y+bv.y; x.z+=v.z+bv.z; x.w+=v.w+bv.w;
            *(float4*)p = x;
        }
    }

    // ===== enc / delta / surprise =====
    fz2(&c2[0][0]);
    g64(xs, enc_w + (size_t)g*8192, 64, 128, wsm, c2, ty, kh2, tx8, tid);
    redK4(&c2[0][0]);
    if (kh2 == 0){
        float ss[4];
        float4 b0 = *(const float4*)&enc_b[g*64 + tx8*4];
        float4 b1 = *(const float4*)&enc_b[g*64 + 32 + tx8*4];
#pragma unroll
        for (int tt=0;tt<4;tt++){
            int t = ty*4+tt; size_t tg = t0+t;
            float4 z0 = pk4(c2[tt][0], c2[tt][1]);
            float4 z1 = pk4(c2[tt][2], c2[tt][3]);
            z0.x+=b0.x; z0.y+=b0.y; z0.z+=b0.z; z0.w+=b0.w;
            z1.x+=b1.x; z1.y+=b1.y; z1.z+=b1.z; z1.w+=b1.w;
            float4 h0 = *(const float4*)&z_hat_prev[(tg*Gn+g)*64 + tx8*4];
            float4 h1 = *(const float4*)&z_hat_prev[(tg*Gn+g)*64 + 32 + tx8*4];
            float4 d0 = make_float4(z0.x-h0.x, z0.y-h0.y, z0.z-h0.z, z0.w-h0.w);
            float4 d1 = make_float4(z1.x-h1.x, z1.y-h1.y, z1.z-h1.z, z1.w-h1.w);
            ss[tt] = d0.x*d0.x+d0.y*d0.y+d0.z*d0.z+d0.w*d0.w
                   + d1.x*d1.x+d1.y*d1.y+d1.z*d1.z+d1.w*d1.w;
            *(float4*)&hs[t*132 + tx8*4] = z0;      *(float4*)&hs[t*132 + 32 + tx8*4] = z1;
            *(float4*)&bC[t*132 + tx8*4] = d0;      *(float4*)&bC[t*132 + 32 + tx8*4] = d1;
            *(float4*)&out[O_Z + (tg*Gn+g)*64 + tx8*4] = z0;
            *(float4*)&out[O_Z + (tg*Gn+g)*64 + 32 + tx8*4] = z1;
        }
#pragma unroll
        for (int tt=0;tt<4;tt++){
            ss[tt] += __shfl_xor_sync(0x000000ffu, ss[tt], 1);
            ss[tt] += __shfl_xor_sync(0x000000ffu, ss[tt], 2);
            ss[tt] += __shfl_xor_sync(0x000000ffu, ss[tt], 4);
        }
        if (tx8 == 0){
#pragma unroll
            for (int tt=0;tt<4;tt++){
                size_t tg = t0 + ty*4 + tt;
                float s = sqrtf(ss[tt]);
                out[O_SURP + tg*Gn + g] = s;
                out[O_S4 + tg*Gn + g] = s;
                out[O_GATE + tg*Gn + g] = fminf(s, 1.f);
            }
        }
    }
    __syncthreads();

    // ===== z_hat (z in hs) =====
    fz2(&c2[0][0]);
    g64(hs, pred_w + (size_t)g*4096, 64, 64, wsm, c2, ty, kh2, tx8, tid);
    redK4(&c2[0][0]);
    if (kh2 < 2){
        int col = kh2*32 + tx8*4;
        float4 bv = *(const float4*)&pred_b[g*64 + col];
#pragma unroll
        for (int tt=0;tt<4;tt++){
            size_t tg = t0 + ty*4 + tt;
            float4 v = pksel(c2[tt], kh2);
            v.x+=bv.x; v.y+=bv.y; v.z+=bv.z; v.w+=bv.w;
            *(float4*)&out[O_ZHAT + (tg*Gn+g)*64 + col] = v;
        }
    }

    // ===== gain (delta in bC) -> hs =====
    fz2(&c2[0][0]);
    g128<false>(bC, gain_w + (size_t)g*8192, 128, 64, wsm, c2, ty, kh, tx, tid);
    redK2(&c2[0][0]);
    {   int col = kh*64 + tx*4;
        float4 bv = *(const float4*)&gain_b[g*128 + col];
#pragma unroll
        for (int tt=0;tt<4;tt++){
            float4 v = pksel(c2[tt], kh);
            float4 o;
            o.x = 1.f + 0.1f*tanhf(v.x+bv.x); o.y = 1.f + 0.1f*tanhf(v.y+bv.y);
            o.z = 1.f + 0.1f*tanhf(v.z+bv.z); o.w = 1.f + 0.1f*tanhf(v.w+bv.w);
            *(float4*)&hs[(ty*4+tt)*132 + col] = o;
        }
    }
    __syncthreads();

    // ===== layernorm * gain -> bC (8 threads/token, 16 cols each) =====
    {
        float s=0.f, sq=0.f; float4 xv[4];
#pragma unroll
        for (int u=0;u<4;u++){
            xv[u] = *(const float4*)&xs[tok*132 + j8*16 + u*4];
            s  += xv[u].x+xv[u].y+xv[u].z+xv[u].w;
            sq += xv[u].x*xv[u].x+xv[u].y*xv[u].y+xv[u].z*xv[u].z+xv[u].w*xv[u].w;
        }
        s  += __shfl_xor_sync(0xffffffffu, s, 1);
        s  += __shfl_xor_sync(0xffffffffu, s, 2);
        s  += __shfl_xor_sync(0xffffffffu, s, 4);
        sq += __shfl_xor_sync(0xffffffffu, sq, 1);
        sq += __shfl_xor_sync(0xffffffffu, sq, 2);
        sq += __shfl_xor_sync(0xffffffffu, sq, 4);
        float mu = s*(1.f/128.f);
        float rstd = rsqrtf(sq*(1.f/128.f) - mu*mu + 1e-5f);
#pragma unroll
        for (int u=0;u<4;u++){
            int cb = j8*16 + u*4;
            float4 w4 = *(const float4*)&ffn_norm_w[g*128 + cb];
            float4 b4 = *(const float4*)&ffn_norm_b[g*128 + cb];
            float4 g4 = *(const float4*)&hs[tok*132 + cb];
            float4 h4;
            h4.x = ((xv[u].x-mu)*rstd*w4.x + b4.x)*g4.x;
            h4.y = ((xv[u].y-mu)*rstd*w4.y + b4.y)*g4.y;
            h4.z = ((xv[u].z-mu)*rstd*w4.z + b4.z)*g4.z;
            h4.w = ((xv[u].w-mu)*rstd*w4.w + b4.w)*g4.w;
            *(float4*)&bC[tok*132 + cb] = h4;
        }
    }

    // ===== FFN: h in bC; gelu -> hs; down accumulates into xs =====
    for (int ch=0; ch<4; ch++){
        fz2(&c2[0][0]);
        g128<false>(bC, ffn_up_w + (size_t)g*65536 + ch*128, 512, 128, wsm, c2, ty, kh, tx, tid);
        redK2(&c2[0][0]);
        {   int col = kh*64 + tx*4;
            float4 bv = *(const float4*)&ffn_up_b[g*512 + ch*128 + col];
#pragma unroll
            for (int tt=0;tt<4;tt++){
                float4 v = pksel(c2[tt], kh);
                float4 o;
                float u0=v.x+bv.x, u1=v.y+bv.y, u2=v.z+bv.z, u3=v.w+bv.w;
                o.x = 0.5f*u0*(1.f+erff(u0*0.70710678f));
                o.y = 0.5f*u1*(1.f+erff(u1*0.70710678f));
                o.z = 0.5f*u2*(1.f+erff(u2*0.70710678f));
                o.w = 0.5f*u3*(1.f+erff(u3*0.70710678f));
                *(float4*)&hs[(ty*4+tt)*132 + col] = o;
            }
        }
        fz2(&c2[0][0]);
        g128<false>(hs, ffn_down_w + (size_t)g*65536 + (size_t)ch*128*128, 128, 128, wsm, c2, ty, kh, tx, tid);
        redK2(&c2[0][0]);
        {   int col = kh*64 + tx*4;
#pragma unroll
            for (int tt=0;tt<4;tt++){
                float* p = &xs[(ty*4+tt)*132 + col];
                float4 x = *(float4*)p;
                float4 v = pksel(c2[tt], kh);
                x.x+=v.x; x.y+=v.y; x.z+=v.z; x.w+=v.w;
                *(float4*)p = x;
            }
        }
    }

    // ===== x_out: add down-bias, store =====
    {   int col = kh*64 + tx*4;
        float4 bv = *(const float4*)&ffn_down_b[g*128 + col];
#pragma unroll
        for (int tt=0;tt<4;tt++){
            int t = ty*4+tt; size_t tg = t0+t;
            float* p = &xs[t*132 + col];
            float4 x = *(float4*)p;
            x.x+=bv.x; x.y+=bv.y; x.z+=bv.z; x.w+=bv.w;
            *(float4*)p = x;
            *(float4*)&out[O_XOUT + (tg*Gn+g)*128 + col] = x;
        }
    }

    // ===== post projection: two 128-wide passes over xs =====
    for (int ph=0; ph<2; ph++){
        fz2(&c2[0][0]);
        g128<true>(xs, post_w + (size_t)g*32896 + ph*128, 257, 128, wsm, c2, ty, kh, tx, tid);
        redK2(&c2[0][0]);
        long long voff = ph ? O_VC : O_VP;
        long long noff = ph ? O_QN : O_KC;
        {   int col = kh*64 + tx*4;
            const float* pb = &post_b[(size_t)g*257 + ph*128 + col];   // stride 257: scalar loads
            float4 bv = make_float4(pb[0], pb[1], pb[2], pb[3]);
#pragma unroll
            for (int tt=0;tt<4;tt++){
                size_t tg = t0 + ty*4 + tt;
                float4 v = pksel(c2[tt], kh);
                v.x+=bv.x; v.y+=bv.y; v.z+=bv.z; v.w+=bv.w;
                if (kh == 0) *(float4*)&hs[(ty*4+tt)*132 + tx*4] = v;
                else *(float4*)&out[voff + (tg*Gn+g)*64 + tx*4] = v;
            }
        }
        __syncthreads();
        {   // normalize hs rows (64 cols) -> out[noff]; 8 threads x 8 floats
            float4 r4[2]; float ss = 0.f;
#pragma unroll
            for (int u4=0;u4<2;u4++){
                r4[u4] = *(const float4*)&hs[tok*132 + j8*8 + u4*4];
                ss += r4[u4].x*r4[u4].x + r4[u4].y*r4[u4].y
                    + r4[u4].z*r4[u4].z + r4[u4].w*r4[u4].w;
            }
            ss += __shfl_xor_sync(0xffffffffu, ss, 1);
            ss += __shfl_xor_sync(0xffffffffu, ss, 2);
            ss += __shfl_xor_sync(0xffffffffu, ss, 4);
            float inv = 1.f/(sqrtf(ss) + 1e-6f);
            size_t tg = t0 + tok;
#pragma unroll
            for (int u4=0;u4<2;u4++){
                float4 v = make_float4(r4[u4].x*inv, r4[u4].y*inv, r4[u4].z*inv, r4[u4].w*inv);
                *(float4*)&out[noff + (tg*Gn+g)*64 + j8*8 + u4*4] = v;
            }
        }
        __syncthreads();
    }

    // ===== w_nov (proj column 256) =====
    if (tid < 128)
        wsm[tid] = post_w[(size_t)g*32896 + (size_t)tid*257 + 256];
    __syncthreads();
    {
        float acc = 0.f;
#pragma unroll
        for (int u=0;u<4;u++){
            float4 xv = *(const float4*)&xs[tok*132 + j8*16 + u*4];
            float4 wv = *(const float4*)&wsm[j8*16 + u*4];
            acc += xv.x*wv.x + xv.y*wv.y + xv.z*wv.z + xv.w*wv.w;
        }
        acc += __shfl_xor_sync(0xffffffffu, acc, 1);
        acc += __shfl_xor_sync(0xffffffffu, acc, 2);
        acc += __shfl_xor_sync(0xffffffffu, acc, 4);
        if (j8 == 0){
            size_t tg = t0 + tok;
            float nv = acc + post_b[(size_t)g*257 + 256];
            out[O_WN + tg*Gn + g] = 1.f/(1.f + expf(-nv));
        }
    }
}

extern "C" void kernel_launch(void* const* d_in, const int* in_sizes, int n_in,
                              void* d_out, int out_size) {
    const float* x_col      = (const float*)d_in[0];
    const float* pm_state   = (const float*)d_in[1];
    const float* em_state   = (const float*)d_in[2];
    const float* z_hat_prev = (const float*)d_in[3];
    const float* ffn_norm_w = (const float*)d_in[4];
    const float* ffn_norm_b = (const float*)d_in[5];
    const float* ffn_up_w   = (const float*)d_in[6];
    const float* ffn_up_b   = (const float*)d_in[7];
    const float* ffn_down_w = (const float*)d_in[8];
    const float* ffn_down_b = (const float*)d_in[9];
    const float* pm_up_w    = (const float*)d_in[10];
    const float* pm_up_b    = (const float*)d_in[11];
    const float* pm_down_w  = (const float*)d_in[12];
    const float* pm_down_b  = (const float*)d_in[13];
    const float* em_up_w    = (const float*)d_in[14];
    const float* em_up_b    = (const float*)d_in[15];
    const float* em_down_w  = (const float*)d_in[16];
    const float* em_down_b  = (const float*)d_in[17];
    const float* post_w     = (const float*)d_in[18];
    const float* post_b     = (const float*)d_in[19];
    const float* enc_w      = (const float*)d_in[20];
    const float* enc_b      = (const float*)d_in[21];
    const float* pred_w     = (const float*)d_in[22];
    const float* pred_b     = (const float*)d_in[23];
    const float* gain_w     = (const float*)d_in[24];
    const float* gain_b     = (const float*)d_in[25];
    float* out = (float*)d_out;

    const int smem = (3*64*132 + 2*1024)*4;  // 109568 B
    cudaFuncSetAttribute(ccg_kernel, cudaFuncAttributeMaxDynamicSharedMemorySize, smem);
    dim3 grid(32, 128);
    ccg_kernel<<<grid, 512, smem>>>(
        x_col, pm_state, em_state, z_hat_prev,
        ffn_norm_w, ffn_norm_b, ffn_up_w, ffn_up_b, ffn_down_w, ffn_down_b,
        pm_up_w, pm_up_b, pm_down_w, pm_down_b,
        em_up_w, em_up_b, em_down_w, em_down_b,
        post_w, post_b, enc_w, enc_b, pred_w, pred_b, gain_w, gain_b,
        out);
}

// round 14
// speedup vs baseline: 1.0002x; 1.0002x over previous
#include <cuda_runtime.h>
#include <math.h>

#define Gn 128
typedef unsigned long long U64;

static const long long O_XOUT=0LL, O_Z=33554432LL, O_ZHAT=50331648LL, O_SURP=67108864LL,
 O_KC=67371008LL, O_VP=84148224LL, O_GATE=100925440LL, O_QN=101187584LL,
 O_VC=117964800LL, O_WN=134742016LL, O_S4=135004160LL;

__device__ __forceinline__ void f2fma(U64& d, U64 a, U64 b){
    asm("fma.rn.f32x2 %0, %1, %2, %0;" : "+l"(d) : "l"(a), "l"(b));
}
__device__ __forceinline__ void f2add(U64& d, U64 a){
    asm("add.rn.f32x2 %0, %0, %1;" : "+l"(d) : "l"(a));
}
__device__ __forceinline__ U64 dup2(float a){
    U64 r; asm("mov.b64 %0, {%1, %1};" : "=l"(r) : "f"(a)); return r;
}
__device__ __forceinline__ float4 pk4(U64 p0, U64 p1){
    float4 v;
    asm("mov.b64 {%0, %1}, %2;" : "=f"(v.x), "=f"(v.y) : "l"(p0));
    asm("mov.b64 {%0, %1}, %2;" : "=f"(v.z), "=f"(v.w) : "l"(p1));
    return v;
}
__device__ __forceinline__ float4 pksel(const U64* c, int flag){
    U64 p0 = flag ? c[2] : c[0];
    U64 p1 = flag ? c[3] : c[1];
    return pk4(p0, p1);
}
__device__ __forceinline__ void cpa16(float* dst, const float* src){
    unsigned d = (unsigned)__cvta_generic_to_shared(dst);
    asm volatile("cp.async.ca.shared.global [%0], [%1], 16;" :: "r"(d), "l"(src) : "memory");
}
__device__ __forceinline__ void cpa4(float* dst, const float* src){
    unsigned d = (unsigned)__cvta_generic_to_shared(dst);
    asm volatile("cp.async.ca.shared.global [%0], [%1], 4;" :: "r"(d), "l"(src) : "memory");
}
__device__ __forceinline__ void cpcommit(){ asm volatile("cp.async.commit_group;" ::: "memory"); }
__device__ __forceinline__ void cpwait0(){ asm volatile("cp.async.wait_group 0;" ::: "memory"); }
__device__ __forceinline__ void fz2(U64* c){
#pragma unroll
    for (int i=0;i<16;i++) c[i]=0ULL;
}
__device__ __forceinline__ void redK2(U64* c){
#pragma unroll
    for (int i=0;i<16;i++) f2add(c[i], __shfl_xor_sync(0xffffffffu, c[i], 16));
}
__device__ __forceinline__ void redK4(U64* c){
#pragma unroll
    for (int i=0;i<16;i++){
        f2add(c[i], __shfl_xor_sync(0xffffffffu, c[i], 8));
        f2add(c[i], __shfl_xor_sync(0xffffffffu, c[i], 16));
    }
}

// ---- inner loops: warp = 4 tokens (ty); lanes split K (interleaved) ----
__device__ __forceinline__ void innU64(const float* As, int kbase, const float* wb, int rbase,
                                       U64 c2[][4], int ty, int tx8){
    float4 a4[4];
#pragma unroll
    for (int tt=0;tt<4;tt++) a4[tt] = *(const float4*)&As[(ty*4+tt)*132 + kbase];
#pragma unroll
    for (int r=0;r<4;r++){
        ulonglong2 w0 = *(const ulonglong2*)&wb[(rbase+r)*64 + tx8*4];
        ulonglong2 w1 = *(const ulonglong2*)&wb[(rbase+r)*64 + 32 + tx8*4];
#pragma unroll
        for (int tt=0;tt<4;tt++){
            U64 a = dup2(((const float*)&a4[tt])[r]);
            f2fma(c2[tt][0],a,w0.x); f2fma(c2[tt][1],a,w0.y);
            f2fma(c2[tt][2],a,w1.x); f2fma(c2[tt][3],a,w1.y);
        }
    }
}
__device__ __forceinline__ void innU128(const float* As, int kbase, const float* wb, int rbase,
                                        U64 c2[][4], int ty, int tx){
#pragma unroll
    for (int rp=0;rp<2;rp++){
        float2 a2[4];
#pragma unroll
        for (int tt=0;tt<4;tt++) a2[tt] = *(const float2*)&As[(ty*4+tt)*132 + kbase + rp*2];
#pragma unroll
        for (int rr=0;rr<2;rr++){
            int r = rp*2+rr;
            ulonglong2 w0 = *(const ulonglong2*)&wb[(rbase+r)*128 + tx*4];
            ulonglong2 w1 = *(const ulonglong2*)&wb[(rbase+r)*128 + 64 + tx*4];
#pragma unroll
            for (int tt=0;tt<4;tt++){
                U64 a = dup2(rr ? a2[tt].y : a2[tt].x);
                f2fma(c2[tt][0],a,w0.x); f2fma(c2[tt][1],a,w0.y);
                f2fma(c2[tt][2],a,w1.x); f2fma(c2[tt][3],a,w1.y);
            }
        }
    }
}

// ---- GEMM drivers: double-buffered cp.async, staging by threads 0-255 ----
__device__ __forceinline__ void g64(const float* As, const float* __restrict__ W, long wst, int K,
                                    float* wsm, U64 c2[][4], int ty, int kh2, int tx8, int tid){
    int nc = K>>4;
    bool st = tid < 256;
    int rr = tid>>4, c4 = (tid&15)*4;
    if (st) cpa16(&wsm[rr*64+c4], &W[(size_t)rr*wst + c4]);
    cpcommit();
    for (int c=0;c<nc;c++){
        cpwait0(); __syncthreads();
        if (c+1<nc){
            if (st) cpa16(&wsm[((c+1)&1)*1024 + rr*64+c4], &W[(size_t)((c+1)*16+rr)*wst + c4]);
            cpcommit();
        }
        innU64(As, c*16 + kh2*4, wsm + (c&1)*1024, kh2*4, c2, ty, tx8);
    }
    __syncthreads();
}
__device__ __forceinline__ void g64T(const float* As, const float* __restrict__ S, int slots,
                                     float* wsm, U64 c2[][4], int ty, int kh2, int tx8, int tid){
    int s = tid&63, q = (tid>>6)&3;
    bool st = tid < 256;
    for (int c=0;c<4;c++){
        float4 v = make_float4(0.f,0.f,0.f,0.f);
        if (st && s < slots) v = *(const float4*)&S[s*64 + c*16 + q*4];
        __syncthreads();
        if (st){
            wsm[(q*4+0)*64+s]=v.x; wsm[(q*4+1)*64+s]=v.y;
            wsm[(q*4+2)*64+s]=v.z; wsm[(q*4+3)*64+s]=v.w;
        }
        __syncthreads();
        innU64(As, c*16 + kh2*4, wsm, kh2*4, c2, ty, tx8);
    }
    __syncthreads();
}
template<bool UA>
__device__ __forceinline__ void g128(const float* As, const float* __restrict__ W, long wst, int K,
                                     float* wsm, U64 c2[][4], int ty, int kh, int tx, int tid){
    int nc = K>>3;
    bool st = tid < 256;
    int rr8 = tid>>5, c48 = (tid&31)*4;
#define STAGE128(cc, buf) do { \
    if (st){ \
        if (UA){ \
            for (int j=0;j<4;j++){ int flat=tid+256*j; int r_=flat>>7, col_=flat&127; \
                cpa4(&(buf)[r_*128+col_], &W[(size_t)((cc)*8 + r_)*wst + col_]); } \
        } else { \
            cpa16(&(buf)[rr8*128+c48], &W[(size_t)((cc)*8 + rr8)*wst + c48]); \
        } \
    } \
    cpcommit(); } while(0)
    STAGE128(0, wsm);
    for (int c=0;c<nc;c++){
        cpwait0(); __syncthreads();
        if (c+1<nc) STAGE128(c+1, wsm + ((c+1)&1)*1024);
        innU128(As, c*8 + kh*4, wsm + (c&1)*1024, kh*4, c2, ty, tx);
    }
    __syncthreads();
#undef STAGE128
}

// ---- epilogues ----
__device__ __forceinline__ void eps64(U64 c2[][4], float* buf, const float* bias,
                                      int ty, int kh2, int tx8){
    if (kh2 >= 2) return;
    int col = kh2*32 + tx8*4;
    float4 bv = bias ? *(const float4*)&bias[col] : make_float4(0.f,0.f,0.f,0.f);
#pragma unroll
    for (int tt=0;tt<4;tt++){
        float4 v = pksel(c2[tt], kh2);
        v.x+=bv.x; v.y+=bv.y; v.z+=bv.z; v.w+=bv.w;
        *(float4*)&buf[(ty*4+tt)*132 + col] = v;
    }
}

template <int SLOTS>
__device__ __forceinline__ void softmax8(float* buf, int tok, int j8){
    const int nS = SLOTS/8;
    float l[nS]; float m = -1e30f;
#pragma unroll
    for (int i=0;i<nS;i++){ l[i] = buf[tok*132 + j8*nS + i]*0.125f; m = fmaxf(m, l[i]); }
    m = fmaxf(m, __shfl_xor_sync(0xffffffffu, m, 1));
    m = fmaxf(m, __shfl_xor_sync(0xffffffffu, m, 2));
    m = fmaxf(m, __shfl_xor_sync(0xffffffffu, m, 4));
    float s = 0.f;
#pragma unroll
    for (int i=0;i<nS;i++){ l[i]=expf(l[i]-m); s+=l[i]; }
    s += __shfl_xor_sync(0xffffffffu, s, 1);
    s += __shfl_xor_sync(0xffffffffu, s, 2);
    s += __shfl_xor_sync(0xffffffffu, s, 4);
    float inv = 1.f/s;
#pragma unroll
    for (int i=0;i<nS;i++) buf[tok*132 + j8*nS + i] = l[i]*inv;
}

__global__ void __launch_bounds__(512, 2)
ccg_kernel(
    const float* __restrict__ x_col, const float* __restrict__ pm_state,
    const float* __restrict__ em_state, const float* __restrict__ z_hat_prev,
    const float* __restrict__ ffn_norm_w, const float* __restrict__ ffn_norm_b,
    const float* __restrict__ ffn_up_w, const float* __restrict__ ffn_up_b,
    const float* __restrict__ ffn_down_w, const float* __restrict__ ffn_down_b,
    const float* __restrict__ pm_up_w, const float* __restrict__ pm_up_b,
    const float* __restrict__ pm_down_w, const float* __restrict__ pm_down_b,
    const float* __restrict__ em_up_w, const float* __restrict__ em_up_b,
    const float* __restrict__ em_down_w, const float* __restrict__ em_down_b,
    const float* __restrict__ post_w, const float* __restrict__ post_b,
    const float* __restrict__ enc_w, const float* __restrict__ enc_b,
    const float* __restrict__ pred_w, const float* __restrict__ pred_b,
    const float* __restrict__ gain_w, const float* __restrict__ gain_b,
    float* __restrict__ out)
{
    extern __shared__ float smf[];
    float* xs  = smf;               // 64 x 132 residual
    float* hs  = xs + 64*132;       // 64 x 132 logits/z/gain/gelu/post-k
    float* bC  = hs + 64*132;       // 64 x 132 q/apply/delta/h
    float* wsm = bC + 64*132;       // 2 x 1024 weight staging

    const int tid = threadIdx.x;
    const int lane = tid & 31, ty = tid >> 5;        // warp = 4 tokens
    const int kh = lane >> 4, tx = lane & 15;
    const int kh2 = lane >> 3, tx8 = lane & 7;
    const int tok = tid >> 3, j8 = tid & 7;          // 8 threads / token
    const int g = blockIdx.y, t0 = blockIdx.x*64;
    const int bs = t0 >> 9, bidx = g >> 4;

    U64 c2[4][4];

#pragma unroll
    for (int jj=0;jj<4;jj++){
        int flat = tid + 512*jj, r = flat>>5, c4 = flat&31;
        *(float4*)&xs[r*132 + c4*4] =
            *(const float4*)&x_col[((size_t)(t0+r)*Gn + g)*128 + c4*4];
    }

    // ===== pm stage =====
    fz2(&c2[0][0]);
    g64(xs, pm_up_w + (size_t)g*8192, 64, 128, wsm, c2, ty, kh2, tx8, tid);
    redK4(&c2[0][0]);
    eps64(c2, bC, pm_up_b + g*64, ty, kh2, tx8);

    const float* Spm = pm_state + (size_t)((bs*8 + bidx)*16)*64;
    fz2(&c2[0][0]);
    g64T(bC, Spm, 16, wsm, c2, ty, kh2, tx8, tid);
    redK4(&c2[0][0]);
    eps64(c2, hs, (const float*)0, ty, kh2, tx8);
    __syncthreads();
    softmax8<16>(hs, tok, j8);
    __syncthreads();

    fz2(&c2[0][0]);
    g64(hs, Spm, 64, 16, wsm, c2, ty, kh2, tx8, tid);
    redK4(&c2[0][0]);
    eps64(c2, bC, (const float*)0, ty, kh2, tx8);

    fz2(&c2[0][0]);
    g128<false>(bC, pm_down_w + (size_t)g*8192, 128, 64, wsm, c2, ty, kh, tx, tid);
    redK2(&c2[0][0]);
    {   int col = kh*64 + tx*4;
        float4 bv = *(const float4*)&pm_down_b[g*128 + col];
#pragma unroll
        for (int tt=0;tt<4;tt++){
            float* p = &xs[(ty*4+tt)*132 + col];
            float4 x = *(float4*)p; float4 v = pksel(c2[tt], kh);
            x.x+=v.x+bv.x; x.y+=v.y+bv.y; x.z+=v.z+bv.z; x.w+=v.w+bv.w;
            *(float4*)p = x;
        }
    }

    // ===== em stage =====
    fz2(&c2[0][0]);
    g64(xs, em_up_w + (size_t)g*8192, 64, 128, wsm, c2, ty, kh2, tx8, tid);
    redK4(&c2[0][0]);
    eps64(c2, bC, em_up_b + g*64, ty, kh2, tx8);

    const float* Sem = em_state + (size_t)((bs*8 + bidx)*64)*64;
    fz2(&c2[0][0]);
    g64T(bC, Sem, 64, wsm, c2, ty, kh2, tx8, tid);
    redK4(&c2[0][0]);
    eps64(c2, hs, (const float*)0, ty, kh2, tx8);
    __syncthreads();
    softmax8<64>(hs, tok, j8);
    __syncthreads();

    fz2(&c2[0][0]);
    g64(hs, Sem, 64, 64, wsm, c2, ty, kh2, tx8, tid);
    redK4(&c2[0][0]);
    eps64(c2, bC, (const float*)0, ty, kh2, tx8);

    fz2(&c2[0][0]);
    g128<false>(bC, em_down_w + (size_t)g*8192, 128, 64, wsm, c2, ty, kh, tx, tid);
    redK2(&c2[0][0]);
    {   int col = kh*64 + tx*4;
        float4 bv = *(const float4*)&em_down_b[g*128 + col];
#pragma unroll
        for (int tt=0;tt<4;tt++){
            float* p = &xs[(ty*4+tt)*132 + col];
            float4 x = *(float4*)p; float4 v = pksel(c2[tt], kh);
            x.x+=v.x+bv.x; x.y+=v.y+bv.y; x.z+=v.z+bv.z; x.w+=v.w+bv.w;
            *(float4*)p = x;
        }
    }

    // ===== enc / delta / surprise =====
    fz2(&c2[0][0]);
    g64(xs, enc_w + (size_t)g*8192, 64, 128, wsm, c2, ty, kh2, tx8, tid);
    redK4(&c2[0][0]);
    if (kh2 == 0){
        float ss[4];
        float4 b0 = *(const float4*)&enc_b[g*64 + tx8*4];
        float4 b1 = *(const float4*)&enc_b[g*64 + 32 + tx8*4];
#pragma unroll
        for (int tt=0;tt<4;tt++){
            int t = ty*4+tt; size_t tg = t0+t;
            float4 z0 = pk4(c2[tt][0], c2[tt][1]);
            float4 z1 = pk4(c2[tt][2], c2[tt][3]);
            z0.x+=b0.x; z0.y+=b0.y; z0.z+=b0.z; z0.w+=b0.w;
            z1.x+=b1.x; z1.y+=b1.y; z1.z+=b1.z; z1.w+=b1.w;
            float4 h0 = *(const float4*)&z_hat_prev[(tg*Gn+g)*64 + tx8*4];
            float4 h1 = *(const float4*)&z_hat_prev[(tg*Gn+g)*64 + 32 + tx8*4];
            float4 d0 = make_float4(z0.x-h0.x, z0.y-h0.y, z0.z-h0.z, z0.w-h0.w);
            float4 d1 = make_float4(z1.x-h1.x, z1.y-h1.y, z1.z-h1.z, z1.w-h1.w);
            ss[tt] = d0.x*d0.x+d0.y*d0.y+d0.z*d0.z+d0.w*d0.w
                   + d1.x*d1.x+d1.y*d1.y+d1.z*d1.z+d1.w*d1.w;
            *(float4*)&hs[t*132 + tx8*4] = z0;      *(float4*)&hs[t*132 + 32 + tx8*4] = z1;
            *(float4*)&bC[t*132 + tx8*4] = d0;      *(float4*)&bC[t*132 + 32 + tx8*4] = d1;
            *(float4*)&out[O_Z + (tg*Gn+g)*64 + tx8*4] = z0;
            *(float4*)&out[O_Z + (tg*Gn+g)*64 + 32 + tx8*4] = z1;
        }
#pragma unroll
        for (int tt=0;tt<4;tt++){
            ss[tt] += __shfl_xor_sync(0x000000ffu, ss[tt], 1);
            ss[tt] += __shfl_xor_sync(0x000000ffu, ss[tt], 2);
            ss[tt] += __shfl_xor_sync(0x000000ffu, ss[tt], 4);
        }
        if (tx8 == 0){
#pragma unroll
            for (int tt=0;tt<4;tt++){
                size_t tg = t0 + ty*4 + tt;
                float s = sqrtf(ss[tt]);
                out[O_SURP + tg*Gn + g] = s;
                out[O_S4 + tg*Gn + g] = s;
                out[O_GATE + tg*Gn + g] = fminf(s, 1.f);
            }
        }
    }
    __syncthreads();

    // ===== z_hat (z in hs) =====
    fz2(&c2[0][0]);
    g64(hs, pred_w + (size_t)g*4096, 64, 64, wsm, c2, ty, kh2, tx8, tid);
    redK4(&c2[0][0]);
    if (kh2 < 2){
        int col = kh2*32 + tx8*4;
        float4 bv = *(const float4*)&pred_b[g*64 + col];
#pragma unroll
        for (int tt=0;tt<4;tt++){
            size_t tg = t0 + ty*4 + tt;
            float4 v = pksel(c2[tt], kh2);
            v.x+=bv.x; v.y+=bv.y; v.z+=bv.z; v.w+=bv.w;
            *(float4*)&out[O_ZHAT + (tg*Gn+g)*64 + col] = v;
        }
    }

    // ===== gain (delta in bC) -> hs =====
    fz2(&c2[0][0]);
    g128<false>(bC, gain_w + (size_t)g*8192, 128, 64, wsm, c2, ty, kh, tx, tid);
    redK2(&c2[0][0]);
    {   int col = kh*64 + tx*4;
        float4 bv = *(const float4*)&gain_b[g*128 + col];
#pragma unroll
        for (int tt=0;tt<4;tt++){
            float4 v = pksel(c2[tt], kh);
            float4 o;
            o.x = 1.f + 0.1f*tanhf(v.x+bv.x); o.y = 1.f + 0.1f*tanhf(v.y+bv.y);
            o.z = 1.f + 0.1f*tanhf(v.z+bv.z); o.w = 1.f + 0.1f*tanhf(v.w+bv.w);
            *(float4*)&hs[(ty*4+tt)*132 + col] = o;
        }
    }
    __syncthreads();

    // ===== layernorm * gain -> bC (8 threads/token, 16 cols each) =====
    {
        float s=0.f, sq=0.f; float4 xv[4];
#pragma unroll
        for (int u=0;u<4;u++){
            xv[u] = *(const float4*)&xs[tok*132 + j8*16 + u*4];
            s  += xv[u].x+xv[u].y+xv[u].z+xv[u].w;
            sq += xv[u].x*xv[u].x+xv[u].y*xv[u].y+xv[u].z*xv[u].z+xv[u].w*xv[u].w;
        }
        s  += __shfl_xor_sync(0xffffffffu, s, 1);
        s  += __shfl_xor_sync(0xffffffffu, s, 2);
        s  += __shfl_xor_sync(0xffffffffu, s, 4);
        sq += __shfl_xor_sync(0xffffffffu, sq, 1);
        sq += __shfl_xor_sync(0xffffffffu, sq, 2);
        sq += __shfl_xor_sync(0xffffffffu, sq, 4);
        float mu = s*(1.f/128.f);
        float rstd = rsqrtf(sq*(1.f/128.f) - mu*mu + 1e-5f);
#pragma unroll
        for (int u=0;u<4;u++){
            int cb = j8*16 + u*4;
            float4 w4 = *(const float4*)&ffn_norm_w[g*128 + cb];
            float4 b4 = *(const float4*)&ffn_norm_b[g*128 + cb];
            float4 g4 = *(const float4*)&hs[tok*132 + cb];
            float4 h4;
            h4.x = ((xv[u].x-mu)*rstd*w4.x + b4.x)*g4.x;
            h4.y = ((xv[u].y-mu)*rstd*w4.y + b4.y)*g4.y;
            h4.z = ((xv[u].z-mu)*rstd*w4.z + b4.z)*g4.z;
            h4.w = ((xv[u].w-mu)*rstd*w4.w + b4.w)*g4.w;
            *(float4*)&bC[tok*132 + cb] = h4;
        }
    }

    // ===== FFN: h in bC; gelu -> hs; down accumulates into xs =====
    for (int ch=0; ch<4; ch++){
        fz2(&c2[0][0]);
        g128<false>(bC, ffn_up_w + (size_t)g*65536 + ch*128, 512, 128, wsm, c2, ty, kh, tx, tid);
        redK2(&c2[0][0]);
        {   int col = kh*64 + tx*4;
            float4 bv = *(const float4*)&ffn_up_b[g*512 + ch*128 + col];
#pragma unroll
            for (int tt=0;tt<4;tt++){
                float4 v = pksel(c2[tt], kh);
                float4 o;
                float u0=v.x+bv.x, u1=v.y+bv.y, u2=v.z+bv.z, u3=v.w+bv.w;
                o.x = 0.5f*u0*(1.f+erff(u0*0.70710678f));
                o.y = 0.5f*u1*(1.f+erff(u1*0.70710678f));
                o.z = 0.5f*u2*(1.f+erff(u2*0.70710678f));
                o.w = 0.5f*u3*(1.f+erff(u3*0.70710678f));
                *(float4*)&hs[(ty*4+tt)*132 + col] = o;
            }
        }
        fz2(&c2[0][0]);
        g128<false>(hs, ffn_down_w + (size_t)g*65536 + (size_t)ch*128*128, 128, 128, wsm, c2, ty, kh, tx, tid);
        redK2(&c2[0][0]);
        {   int col = kh*64 + tx*4;
#pragma unroll
            for (int tt=0;tt<4;tt++){
                float* p = &xs[(ty*4+tt)*132 + col];
                float4 x = *(float4*)p;
                float4 v = pksel(c2[tt], kh);
                x.x+=v.x; x.y+=v.y; x.z+=v.z; x.w+=v.w;
                *(float4*)p = x;
            }
        }
    }

    // ===== x_out: add down-bias, store =====
    {   int col = kh*64 + tx*4;
        float4 bv = *(const float4*)&ffn_down_b[g*128 + col];
#pragma unroll
        for (int tt=0;tt<4;tt++){
            int t = ty*4+tt; size_t tg = t0+t;
            float* p = &xs[t*132 + col];
            float4 x = *(float4*)p;
            x.x+=bv.x; x.y+=bv.y; x.z+=bv.z; x.w+=bv.w;
            *(float4*)p = x;
            *(float4*)&out[O_XOUT + (tg*Gn+g)*128 + col] = x;
        }
    }

    // ===== post projection: two 128-wide passes over xs =====
    for (int ph=0; ph<2; ph++){
        fz2(&c2[0][0]);
        g128<true>(xs, post_w + (size_t)g*32896 + ph*128, 257, 128, wsm, c2, ty, kh, tx, tid);
        redK2(&c2[0][0]);
        long long voff = ph ? O_VC : O_VP;
        long long noff = ph ? O_QN : O_KC;
        {   int col = kh*64 + tx*4;
            const float* pb = &post_b[(size_t)g*257 + ph*128 + col];   // stride 257: scalar loads
            float4 bv = make_float4(pb[0], pb[1], pb[2], pb[3]);
#pragma unroll
            for (int tt=0;tt<4;tt++){
                size_t tg = t0 + ty*4 + tt;
                float4 v = pksel(c2[tt], kh);
                v.x+=bv.x; v.y+=bv.y; v.z+=bv.z; v.w+=bv.w;
                if (kh == 0) *(float4*)&hs[(ty*4+tt)*132 + tx*4] = v;
                else *(float4*)&out[voff + (tg*Gn+g)*64 + tx*4] = v;
            }
        }
        __syncthreads();
        {   // normalize hs rows (64 cols) -> out[noff]; 8 threads x 8 floats
            float4 r4[2]; float ss = 0.f;
#pragma unroll
            for (int u4=0;u4<2;u4++){
                r4[u4] = *(const float4*)&hs[tok*132 + j8*8 + u4*4];
                ss += r4[u4].x*r4[u4].x + r4[u4].y*r4[u4].y
                    + r4[u4].z*r4[u4].z + r4[u4].w*r4[u4].w;
            }
            ss += __shfl_xor_sync(0xffffffffu, ss, 1);
            ss += __shfl_xor_sync(0xffffffffu, ss, 2);
            ss += __shfl_xor_sync(0xffffffffu, ss, 4);
            float inv = 1.f/(sqrtf(ss) + 1e-6f);
            size_t tg = t0 + tok;
#pragma unroll
            for (int u4=0;u4<2;u4++){
                float4 v = make_float4(r4[u4].x*inv, r4[u4].y*inv, r4[u4].z*inv, r4[u4].w*inv);
                *(float4*)&out[noff + (tg*Gn+g)*64 + j8*8 + u4*4] = v;
            }
        }
        __syncthreads();
    }

    // ===== w_nov (proj column 256) =====
    if (tid < 128)
        wsm[tid] = post_w[(size_t)g*32896 + (size_t)tid*257 + 256];
    __syncthreads();
    {
        float acc = 0.f;
#pragma unroll
        for (int u=0;u<4;u++){
            float4 xv = *(const float4*)&xs[tok*132 + j8*16 + u*4];
            float4 wv = *(const float4*)&wsm[j8*16 + u*4];
            acc += xv.x*wv.x + xv.y*wv.y + xv.z*wv.z + xv.w*wv.w;
        }
        acc += __shfl_xor_sync(0xffffffffu, acc, 1);
        acc += __shfl_xor_sync(0xffffffffu, acc, 2);
        acc += __shfl_xor_sync(0xffffffffu, acc, 4);
        if (j8 == 0){
            size_t tg = t0 + tok;
            float nv = acc + post_b[(size_t)g*257 + 256];
            out[O_WN + tg*Gn + g] = 1.f/(1.f + expf(-nv));
        }
    }
}

extern "C" void kernel_launch(void* const* d_in, const int* in_sizes, int n_in,
                              void* d_out, int out_size) {
    const float* x_col      = (const float*)d_in[0];
    const float* pm_state   = (const float*)d_in[1];
    const float* em_state   = (const float*)d_in[2];
    const float* z_hat_prev = (const float*)d_in[3];
    const float* ffn_norm_w = (const float*)d_in[4];
    const float* ffn_norm_b = (const float*)d_in[5];
    const float* ffn_up_w   = (const float*)d_in[6];
    const float* ffn_up_b   = (const float*)d_in[7];
    const float* ffn_down_w = (const float*)d_in[8];
    const float* ffn_down_b = (const float*)d_in[9];
    const float* pm_up_w    = (const float*)d_in[10];
    const float* pm_up_b    = (const float*)d_in[11];
    const float* pm_down_w  = (const float*)d_in[12];
    const float* pm_down_b  = (const float*)d_in[13];
    const float* em_up_w    = (const float*)d_in[14];
    const float* em_up_b    = (const float*)d_in[15];
    const float* em_down_w  = (const float*)d_in[16];
    const float* em_down_b  = (const float*)d_in[17];
    const float* post_w     = (const float*)d_in[18];
    const float* post_b     = (const float*)d_in[19];
    const float* enc_w      = (const float*)d_in[20];
    const float* enc_b      = (const float*)d_in[21];
    const float* pred_w     = (const float*)d_in[22];
    const float* pred_b     = (const float*)d_in[23];
    const float* gain_w     = (const float*)d_in[24];
    const float* gain_b     = (const float*)d_in[25];
    float* out = (float*)d_out;

    const int smem = (3*64*132 + 2*1024)*4;  // 109568 B
    cudaFuncSetAttribute(ccg_kernel, cudaFuncAttributeMaxDynamicSharedMemorySize, smem);
    dim3 grid(32, 128);
    ccg_kernel<<<grid, 512, smem>>>(
        x_col, pm_state, em_state, z_hat_prev,
        ffn_norm_w, ffn_norm_b, ffn_up_w, ffn_up_b, ffn_down_w, ffn_down_b,
        pm_up_w, pm_up_b, pm_down_w, pm_down_b,
        em_up_w, em_up_b, em_down_w, em_down_b,
        post_w, post_b, enc_w, enc_b, pred_w, pred_b, gain_w, gain_b,
        out);
}

// round 15
// speedup vs baseline: 1.4930x; 1.4927x over previous
#include <cuda_runtime.h>
#include <math.h>

#define Gn 128
typedef unsigned long long U64;

static const long long O_XOUT = 0LL;
static const long long O_Z    = 33554432LL;
static const long long O_ZHAT = 50331648LL;
static const long long O_SURP = 67108864LL;
static const long long O_KC   = 67371008LL;
static const long long O_VP   = 84148224LL;
static const long long O_GATE = 100925440LL;
static const long long O_QN   = 101187584LL;
static const long long O_VC   = 117964800LL;
static const long long O_WN   = 134742016LL;
static const long long O_S4   = 135004160LL;

__device__ __forceinline__ void f2fma(U64& d, U64 a, U64 b) {
    asm("fma.rn.f32x2 %0, %1, %2, %0;" : "+l"(d) : "l"(a), "l"(b));
}
__device__ __forceinline__ U64 dup2(float a) {
    U64 r; asm("mov.b64 %0, {%1, %1};" : "=l"(r) : "f"(a)); return r;
}
__device__ __forceinline__ float2 unpk(U64 v) {
    float2 f; asm("mov.b64 {%0, %1}, %2;" : "=f"(f.x), "=f"(f.y) : "l"(v)); return f;
}
__device__ __forceinline__ void cpa16(float* dst, const float* src) {
    unsigned d = (unsigned)__cvta_generic_to_shared(dst);
    asm volatile("cp.async.ca.shared.global [%0], [%1], 16;" :: "r"(d), "l"(src) : "memory");
}
__device__ __forceinline__ void cpa4(float* dst, const float* src) {
    unsigned d = (unsigned)__cvta_generic_to_shared(dst);
    asm volatile("cp.async.ca.shared.global [%0], [%1], 4;" :: "r"(d), "l"(src) : "memory");
}
__device__ __forceinline__ void cpcommit() { asm volatile("cp.async.commit_group;" ::: "memory"); }
__device__ __forceinline__ void cpwait0()  { asm volatile("cp.async.wait_group 0;" ::: "memory"); }

// tf32 tensor-core mma: D += A(16x8 row) * B(8x8 col)
__device__ __forceinline__ void mma_tf32(float* d, const unsigned* a, unsigned b0, unsigned b1) {
    asm volatile("mma.sync.aligned.m16n8k8.row.col.f32.tf32.tf32.f32 "
        "{%0,%1,%2,%3}, {%4,%5,%6,%7}, {%8,%9}, {%0,%1,%2,%3};"
        : "+f"(d[0]), "+f"(d[1]), "+f"(d[2]), "+f"(d[3])
        : "r"(a[0]), "r"(a[1]), "r"(a[2]), "r"(a[3]), "r"(b0), "r"(b1));
}
__device__ __forceinline__ unsigned cvt_tf32(float f) {
    unsigned u; asm("cvt.rna.tf32.f32 %0, %1;" : "=r"(u) : "f"(f)); return u;
}
__device__ __forceinline__ float gelu1(float u) {
    return 0.5f * u * (1.f + erff(u * 0.70710678f));
}

// ---------- staging (R4) ----------
__device__ __forceinline__ void st64(const float* __restrict__ W, long wst, int k0,
                                     float* buf, int tid) {
    int r = tid >> 4, cc = tid & 15;
    cpa16(&buf[r * 68 + cc * 4], &W[(size_t)(k0 + r) * wst + cc * 4]);
    cpcommit();
}
__device__ __forceinline__ void st128(const float* __restrict__ W, long wst, int k0,
                                      float* buf, int tid) {
    int r = tid >> 5, c = tid & 31;
    int half = c >> 4, c4 = c & 15;
    cpa16(&buf[r * 136 + half * 68 + c4 * 4], &W[(size_t)(k0 + r) * wst + c * 4]);
    cpcommit();
}
__device__ __forceinline__ void st128u(const float* __restrict__ W, long wst, int k0,
                                       float* buf, int tid) {
#pragma unroll
    for (int j = 0; j < 4; j++) {
        int flat = tid + 256 * j;
        int r = flat >> 7, col = flat & 127;
        cpa4(&buf[r * 136 + col + ((col >> 6) << 2)], &W[(size_t)(k0 + r) * wst + col]);
    }
    cpcommit();
}

// ---------- FFMA GEMM cores (R4) ----------
__device__ __forceinline__ void inner64(const float* __restrict__ As, int sas, int k0,
                                        const float* wb, U64 c2[][2], int ty, int tx) {
#pragma unroll
    for (int i4 = 0; i4 < 4; i4++) {
        float4 a4[4];
#pragma unroll
        for (int tt = 0; tt < 4; tt++)
            a4[tt] = *(const float4*)&As[(ty * 4 + tt) * sas + k0 + i4 * 4];
#pragma unroll
        for (int ii = 0; ii < 4; ii++) {
            ulonglong2 w = *(const ulonglong2*)&wb[(i4 * 4 + ii) * 68 + tx * 4];
#pragma unroll
            for (int tt = 0; tt < 4; tt++) {
                U64 a = dup2(((const float*)&a4[tt])[ii]);
                f2fma(c2[tt][0], a, w.x);
                f2fma(c2[tt][1], a, w.y);
            }
        }
    }
}
__device__ __forceinline__ void gemm64(const float* __restrict__ As, int sas,
                                       const float* __restrict__ W, long wst, int K,
                                       float* wsm, U64 c2[][2], int ty, int tx, int tid) {
    int nc = K >> 4;
    st64(W, wst, 0, wsm, tid);
    for (int c = 0; c < nc; c++) {
        cpwait0();
        __syncthreads();
        if (c + 1 < nc) st64(W, wst, (c + 1) << 4, wsm + ((c + 1) & 1) * 1088, tid);
        inner64(As, sas, c << 4, wsm + (c & 1) * 1088, c2, ty, tx);
    }
    __syncthreads();
}
__device__ __forceinline__ void gemm64T(const float* __restrict__ As, int sas,
                                        const float* __restrict__ S, int slots, int K,
                                        float* wsm, U64 c2[][2], int ty, int tx, int tid) {
    for (int k0 = 0; k0 < K; k0 += 16) {
        int s = tid & 63, k4 = tid >> 6;
        float4 v = make_float4(0.f, 0.f, 0.f, 0.f);
        if (s < slots) v = *(const float4*)&S[s * 64 + k0 + k4 * 4];
        __syncthreads();
        wsm[(k4 * 4 + 0) * 68 + s] = v.x;
        wsm[(k4 * 4 + 1) * 68 + s] = v.y;
        wsm[(k4 * 4 + 2) * 68 + s] = v.z;
        wsm[(k4 * 4 + 3) * 68 + s] = v.w;
        __syncthreads();
        inner64(As, sas, k0, wsm, c2, ty, tx);
    }
    __syncthreads();
}
__device__ __forceinline__ void inner128(const float* __restrict__ As, int sas, int k0,
                                         const float* wb, U64 c2[][4], int ty, int tx) {
#pragma unroll
    for (int i4 = 0; i4 < 2; i4++) {
        float4 a4[4];
#pragma unroll
        for (int tt = 0; tt < 4; tt++)
            a4[tt] = *(const float4*)&As[(ty * 4 + tt) * sas + k0 + i4 * 4];
#pragma unroll
        for (int ii = 0; ii < 4; ii++) {
            ulonglong2 w0 = *(const ulonglong2*)&wb[(i4 * 4 + ii) * 136 + tx * 4];
            ulonglong2 w1 = *(const ulonglong2*)&wb[(i4 * 4 + ii) * 136 + 68 + tx * 4];
#pragma unroll
            for (int tt = 0; tt < 4; tt++) {
                U64 a = dup2(((const float*)&a4[tt])[ii]);
                f2fma(c2[tt][0], a, w0.x);
                f2fma(c2[tt][1], a, w0.y);
                f2fma(c2[tt][2], a, w1.x);
                f2fma(c2[tt][3], a, w1.y);
            }
        }
    }
}
__device__ __forceinline__ void gemm128(const float* __restrict__ As, int sas,
                                        const float* __restrict__ W, long wst, int K,
                                        float* wsm, U64 c2[][4], int ty, int tx, int tid) {
    int nc = K >> 3;
    st128(W, wst, 0, wsm, tid);
    for (int c = 0; c < nc; c++) {
        cpwait0();
        __syncthreads();
        if (c + 1 < nc) st128(W, wst, (c + 1) << 3, wsm + ((c + 1) & 1) * 1088, tid);
        inner128(As, sas, c << 3, wsm + (c & 1) * 1088, c2, ty, tx);
    }
    __syncthreads();
}
__device__ __forceinline__ void gemm128u(const float* __restrict__ As, int sas,
                                         const float* __restrict__ W, long wst, int K,
                                         float* wsm, U64 c2[][4], int ty, int tx, int tid) {
    int nc = K >> 3;
    st128u(W, wst, 0, wsm, tid);
    for (int c = 0; c < nc; c++) {
        cpwait0();
        __syncthreads();
        if (c + 1 < nc) st128u(W, wst, (c + 1) << 3, wsm + ((c + 1) & 1) * 1088, tid);
        inner128(As, sas, c << 3, wsm + (c & 1) * 1088, c2, ty, tx);
    }
    __syncthreads();
}
__device__ __forceinline__ void fz2(U64* c, int n) {
    for (int i = 0; i < n; i++) c[i] = 0ULL;
}
__device__ __forceinline__ void up2(const U64* c2, float* o) {
    float2 a = unpk(c2[0]), b = unpk(c2[1]);
    o[0] = a.x; o[1] = a.y; o[2] = b.x; o[3] = b.y;
}
template <int SLOTS>
__device__ __forceinline__ void softmax_q(float* buf, int tok, int jq) {
    const int nS = SLOTS / 4;
    float l[nS];
    float m = -1e30f;
#pragma unroll
    for (int i = 0; i < nS; i++) {
        l[i] = buf[tok * 136 + jq * nS + i] * 0.125f;
        m = fmaxf(m, l[i]);
    }
    m = fmaxf(m, __shfl_xor_sync(0xffffffffu, m, 1));
    m = fmaxf(m, __shfl_xor_sync(0xffffffffu, m, 2));
    float s = 0.f;
#pragma unroll
    for (int i = 0; i < nS; i++) { l[i] = expf(l[i] - m); s += l[i]; }
    s += __shfl_xor_sync(0xffffffffu, s, 1);
    s += __shfl_xor_sync(0xffffffffu, s, 2);
    float inv = 1.f / s;
#pragma unroll
    for (int i = 0; i < nS; i++) buf[tok * 136 + jq * nS + i] = l[i] * inv;
}

__global__ void __launch_bounds__(256, 2)
ccg_kernel(
    const float* __restrict__ x_col, const float* __restrict__ pm_state,
    const float* __restrict__ em_state, const float* __restrict__ z_hat_prev,
    const float* __restrict__ ffn_norm_w, const float* __restrict__ ffn_norm_b,
    const float* __restrict__ ffn_up_w, const float* __restrict__ ffn_up_b,
    const float* __restrict__ ffn_down_w, const float* __restrict__ ffn_down_b,
    const float* __restrict__ pm_up_w, const float* __restrict__ pm_up_b,
    const float* __restrict__ pm_down_w, const float* __restrict__ pm_down_b,
    const float* __restrict__ em_up_w, const float* __restrict__ em_up_b,
    const float* __restrict__ em_down_w, const float* __restrict__ em_down_b,
    const float* __restrict__ post_w, const float* __restrict__ post_b,
    const float* __restrict__ enc_w, const float* __restrict__ enc_b,
    const float* __restrict__ pred_w, const float* __restrict__ pred_b,
    const float* __restrict__ gain_w, const float* __restrict__ gain_b,
    float* __restrict__ out)
{
    extern __shared__ float smf[];
    float* xs  = smf;                 // 64 x 132
    float* hs  = xs + 64 * 132;       // 64 x 132
    float* bA  = hs + 64 * 132;       // 64 x 136 (cols 0..67) -- also FFN gelu buf (stride 132)
    float* bB  = bA + 68;             //             (cols 68..135)
    float* wsm = bA + 64 * 136;       // 2 x 1088 weight staging

    const int tid = threadIdx.x;
    const int ty = tid >> 4, tx = tid & 15;
    const int tok = tid >> 2, jq = tid & 3;
    const int g  = blockIdx.y;
    const int t0 = blockIdx.x * 64;
    const int bs = t0 >> 9;
    const int bidx = g >> 4;

    // ---- load x tile ----
#pragma unroll
    for (int jj = 0; jj < 8; jj++) {
        int flat = tid + 256 * jj;
        int r = flat >> 5, c4 = flat & 31;
        *(float4*)&xs[r * 132 + c4 * 4] =
            *(const float4*)&x_col[((size_t)(t0 + r) * Gn + g) * 128 + c4 * 4];
    }

    // ================= pm memory stage =================
    {
        U64 c2[4][2]; fz2(&c2[0][0], 8);
        gemm64(xs, 132, pm_up_w + (size_t)g * 8192, 64, 128, wsm, c2, ty, tx, tid);
#pragma unroll
        for (int tt = 0; tt < 4; tt++) {
            float o[4]; up2(c2[tt], o);
#pragma unroll
            for (int j = 0; j < 4; j++)
                bB[(ty * 4 + tt) * 136 + tx * 4 + j] = o[j] + pm_up_b[g * 64 + tx * 4 + j];
        }
    }
    const float* Spm = pm_state + (size_t)((bs * 8 + bidx) * 16) * 64;
    {
        U64 c2[4][2]; fz2(&c2[0][0], 8);
        gemm64T(bB, 136, Spm, 16, 64, wsm, c2, ty, tx, tid);
        if (tx < 4) {
#pragma unroll
            for (int tt = 0; tt < 4; tt++) {
                float o[4]; up2(c2[tt], o);
#pragma unroll
                for (int j = 0; j < 4; j++) bA[(ty * 4 + tt) * 136 + tx * 4 + j] = o[j];
            }
        }
    }
    __syncthreads();
    softmax_q<16>(bA, tok, jq);
    __syncthreads();
    {
        U64 c2[4][2]; fz2(&c2[0][0], 8);
        gemm64(bA, 136, Spm, 64, 16, wsm, c2, ty, tx, tid);
#pragma unroll
        for (int tt = 0; tt < 4; tt++) {
            float o[4]; up2(c2[tt], o);
#pragma unroll
            for (int j = 0; j < 4; j++) bB[(ty * 4 + tt) * 136 + tx * 4 + j] = o[j];
        }
    }
    {
        U64 c2[4][4]; fz2(&c2[0][0], 16);
        gemm128(bB, 136, pm_down_w + (size_t)g * 8192, 128, 64, wsm, c2, ty, tx, tid);
#pragma unroll
        for (int tt = 0; tt < 4; tt++) {
            float o0[4], o1[4]; up2(&c2[tt][0], o0); up2(&c2[tt][2], o1);
#pragma unroll
            for (int j = 0; j < 4; j++) {
                int a = tx * 4 + j, b = 64 + tx * 4 + j;
                xs[(ty * 4 + tt) * 132 + a] += o0[j] + pm_down_b[g * 128 + a];
                xs[(ty * 4 + tt) * 132 + b] += o1[j] + pm_down_b[g * 128 + b];
            }
        }
    }

    // ================= em memory stage =================
    {
        U64 c2[4][2]; fz2(&c2[0][0], 8);
        gemm64(xs, 132, em_up_w + (size_t)g * 8192, 64, 128, wsm, c2, ty, tx, tid);
#pragma unroll
        for (int tt = 0; tt < 4; tt++) {
            float o[4]; up2(c2[tt], o);
#pragma unroll
            for (int j = 0; j < 4; j++)
                bB[(ty * 4 + tt) * 136 + tx * 4 + j] = o[j] + em_up_b[g * 64 + tx * 4 + j];
        }
    }
    const float* Sem = em_state + (size_t)((bs * 8 + bidx) * 64) * 64;
    {
        U64 c2[4][2]; fz2(&c2[0][0], 8);
        gemm64T(bB, 136, Sem, 64, 64, wsm, c2, ty, tx, tid);
#pragma unroll
        for (int tt = 0; tt < 4; tt++) {
            float o[4]; up2(c2[tt], o);
#pragma unroll
            for (int j = 0; j < 4; j++) bA[(ty * 4 + tt) * 136 + tx * 4 + j] = o[j];
        }
    }
    __syncthreads();
    softmax_q<64>(bA, tok, jq);
    __syncthreads();
    {
        U64 c2[4][2]; fz2(&c2[0][0], 8);
        gemm64(bA, 136, Sem, 64, 64, wsm, c2, ty, tx, tid);
#pragma unroll
        for (int tt = 0; tt < 4; tt++) {
            float o[4]; up2(c2[tt], o);
#pragma unroll
            for (int j = 0; j < 4; j++) bB[(ty * 4 + tt) * 136 + tx * 4 + j] = o[j];
        }
    }
    {
        U64 c2[4][4]; fz2(&c2[0][0], 16);
        gemm128(bB, 136, em_down_w + (size_t)g * 8192, 128, 64, wsm, c2, ty, tx, tid);
#pragma unroll
        for (int tt = 0; tt < 4; tt++) {
            float o0[4], o1[4]; up2(&c2[tt][0], o0); up2(&c2[tt][2], o1);
#pragma unroll
            for (int j = 0; j < 4; j++) {
                int a = tx * 4 + j, b = 64 + tx * 4 + j;
                xs[(ty * 4 + tt) * 132 + a] += o0[j] + em_down_b[g * 128 + a];
                xs[(ty * 4 + tt) * 132 + b] += o1[j] + em_down_b[g * 128 + b];
            }
        }
    }

    // ================= enc / delta / surprise =================
    {
        U64 c2[4][2]; fz2(&c2[0][0], 8);
        gemm64(xs, 132, enc_w + (size_t)g * 8192, 64, 128, wsm, c2, ty, tx, tid);
        float sp[4];
#pragma unroll
        for (int tt = 0; tt < 4; tt++) {
            int t = ty * 4 + tt;
            size_t tg = t0 + t;
            float o[4]; up2(c2[tt], o);
            float4 zh4 = *(const float4*)&z_hat_prev[(tg * Gn + g) * 64 + tx * 4];
            float z0 = o[0] + enc_b[g * 64 + tx * 4 + 0];
            float z1 = o[1] + enc_b[g * 64 + tx * 4 + 1];
            float z2 = o[2] + enc_b[g * 64 + tx * 4 + 2];
            float z3 = o[3] + enc_b[g * 64 + tx * 4 + 3];
            bA[t * 136 + tx * 4 + 0] = z0; bA[t * 136 + tx * 4 + 1] = z1;
            bA[t * 136 + tx * 4 + 2] = z2; bA[t * 136 + tx * 4 + 3] = z3;
            float e0 = z0 - zh4.x, e1 = z1 - zh4.y, e2 = z2 - zh4.z, e3 = z3 - zh4.w;
            bB[t * 136 + tx * 4 + 0] = e0; bB[t * 136 + tx * 4 + 1] = e1;
            bB[t * 136 + tx * 4 + 2] = e2; bB[t * 136 + tx * 4 + 3] = e3;
            sp[tt] = e0 * e0 + e1 * e1 + e2 * e2 + e3 * e3;
            *(float4*)&out[O_Z + (tg * Gn + g) * 64 + tx * 4] = make_float4(z0, z1, z2, z3);
        }
#pragma unroll
        for (int tt = 0; tt < 4; tt++) {
            sp[tt] += __shfl_xor_sync(0xffffffffu, sp[tt], 1);
            sp[tt] += __shfl_xor_sync(0xffffffffu, sp[tt], 2);
            sp[tt] += __shfl_xor_sync(0xffffffffu, sp[tt], 4);
            sp[tt] += __shfl_xor_sync(0xffffffffu, sp[tt], 8);
        }
        if (tx == 0) {
#pragma unroll
            for (int tt = 0; tt < 4; tt++) {
                size_t tg = t0 + ty * 4 + tt;
                float s = sqrtf(sp[tt]);
                out[O_SURP + tg * Gn + g] = s;
                out[O_S4 + tg * Gn + g] = s;
                out[O_GATE + tg * Gn + g] = fminf(s, 1.f);
            }
        }
    }

    // ================= gain (from delta in bB) =================
    {
        U64 c2[4][4]; fz2(&c2[0][0], 16);
        gemm128(bB, 136, gain_w + (size_t)g * 8192, 128, 64, wsm, c2, ty, tx, tid);
#pragma unroll
        for (int tt = 0; tt < 4; tt++) {
            float o0[4], o1[4]; up2(&c2[tt][0], o0); up2(&c2[tt][2], o1);
#pragma unroll
            for (int j = 0; j < 4; j++) {
                int a = tx * 4 + j, b = 64 + tx * 4 + j;
                hs[(ty * 4 + tt) * 132 + a] = 1.f + 0.1f * tanhf(o0[j] + gain_b[g * 128 + a]);
                hs[(ty * 4 + tt) * 132 + b] = 1.f + 0.1f * tanhf(o1[j] + gain_b[g * 128 + b]);
            }
        }
    }

    // ================= z_hat (from z in bA) =================
    {
        U64 c2[4][2]; fz2(&c2[0][0], 8);
        gemm64(bA, 136, pred_w + (size_t)g * 4096, 64, 64, wsm, c2, ty, tx, tid);
#pragma unroll
        for (int tt = 0; tt < 4; tt++) {
            size_t tg = t0 + ty * 4 + tt;
            float o[4]; up2(c2[tt], o);
            float4 v;
            v.x = o[0] + pred_b[g * 64 + tx * 4 + 0];
            v.y = o[1] + pred_b[g * 64 + tx * 4 + 1];
            v.z = o[2] + pred_b[g * 64 + tx * 4 + 2];
            v.w = o[3] + pred_b[g * 64 + tx * 4 + 3];
            *(float4*)&out[O_ZHAT + (tg * Gn + g) * 64 + tx * 4] = v;
        }
    }
    __syncthreads();

    // ================= layernorm * gain -> hs (h) =================
    {
        float s = 0.f, sq = 0.f;
        float4 xv[8];
#pragma unroll
        for (int u = 0; u < 8; u++) {
            xv[u] = *(const float4*)&xs[tok * 132 + jq * 32 + u * 4];
            s  += xv[u].x + xv[u].y + xv[u].z + xv[u].w;
            sq += xv[u].x * xv[u].x + xv[u].y * xv[u].y + xv[u].z * xv[u].z + xv[u].w * xv[u].w;
        }
        s  += __shfl_xor_sync(0xffffffffu, s, 1);
        s  += __shfl_xor_sync(0xffffffffu, s, 2);
        sq += __shfl_xor_sync(0xffffffffu, sq, 1);
        sq += __shfl_xor_sync(0xffffffffu, sq, 2);
        float mu = s * (1.f / 128.f);
        float rstd = rsqrtf(sq * (1.f / 128.f) - mu * mu + 1e-5f);
#pragma unroll
        for (int u = 0; u < 8; u++) {
            int cb = jq * 32 + u * 4;
            float4 w4 = *(const float4*)&ffn_norm_w[g * 128 + cb];
            float4 b4 = *(const float4*)&ffn_norm_b[g * 128 + cb];
            float4 g4 = *(const float4*)&hs[tok * 132 + cb];
            float4 h4;
            h4.x = ((xv[u].x - mu) * rstd * w4.x + b4.x) * g4.x;
            h4.y = ((xv[u].y - mu) * rstd * w4.y + b4.y) * g4.y;
            h4.z = ((xv[u].z - mu) * rstd * w4.z + b4.z) * g4.z;
            h4.w = ((xv[u].w - mu) * rstd * w4.w + b4.w) * g4.w;
            *(float4*)&hs[tok * 132 + cb] = h4;
        }
    }

    // ================= FFN via tf32 tensor cores =================
    {
        const int wid = tid >> 5, lane = tid & 31;
        const int gq = lane >> 2, tig = lane & 3;
        const int mrow = (wid & 3) * 16;          // warp's 16-row band
        const int ncol = (wid >> 2) * 64;         // warp's 64-col half
        float* gbuf = bA;                         // gelu buffer, stride 132

        float dC[8][4];
#pragma unroll
        for (int i = 0; i < 8; i++)
#pragma unroll
            for (int j = 0; j < 4; j++) dC[i][j] = 0.f;

        for (int ch = 0; ch < 4; ch++) {
            // ---- up: uC = h(64x128) @ Wup(128 x 128-chunk) ----
            float uC[8][4];
#pragma unroll
            for (int i = 0; i < 8; i++)
#pragma unroll
                for (int j = 0; j < 4; j++) uC[i][j] = 0.f;
            {   int r = tid >> 5, c4 = (tid & 31) * 4;
                cpa16(&wsm[r * 136 + c4], &ffn_up_w[(size_t)g * 65536 + (size_t)r * 512 + ch * 128 + c4]);
                cpcommit();
            }
            for (int ks = 0; ks < 16; ks++) {
                cpwait0(); __syncthreads();
                if (ks + 1 < 16) {
                    int r = tid >> 5, c4 = (tid & 31) * 4;
                    cpa16(&wsm[((ks + 1) & 1) * 1088 + r * 136 + c4],
                          &ffn_up_w[(size_t)g * 65536 + (size_t)((ks + 1) * 8 + r) * 512 + ch * 128 + c4]);
                    cpcommit();
                }
                const float* wb = wsm + (ks & 1) * 1088;
                unsigned A[4];
                A[0] = cvt_tf32(hs[(mrow + gq) * 132 + ks * 8 + tig]);
                A[1] = cvt_tf32(hs[(mrow + gq + 8) * 132 + ks * 8 + tig]);
                A[2] = cvt_tf32(hs[(mrow + gq) * 132 + ks * 8 + tig + 4]);
                A[3] = cvt_tf32(hs[(mrow + gq + 8) * 132 + ks * 8 + tig + 4]);
#pragma unroll
                for (int nt = 0; nt < 8; nt++) {
                    unsigned b0 = __float_as_uint(wb[tig * 136 + ncol + nt * 8 + gq]);
                    unsigned b1 = __float_as_uint(wb[(tig + 4) * 136 + ncol + nt * 8 + gq]);
                    mma_tf32(uC[nt], A, b0, b1);
                }
            }
            __syncthreads();
            // gelu + bias -> gbuf
#pragma unroll
            for (int nt = 0; nt < 8; nt++) {
                int c0 = ncol + nt * 8 + 2 * tig;
                float b0 = ffn_up_b[g * 512 + ch * 128 + c0];
                float b1 = ffn_up_b[g * 512 + ch * 128 + c0 + 1];
                gbuf[(mrow + gq) * 132 + c0]     = gelu1(uC[nt][0] + b0);
                gbuf[(mrow + gq) * 132 + c0 + 1] = gelu1(uC[nt][1] + b1);
                gbuf[(mrow + gq + 8) * 132 + c0]     = gelu1(uC[nt][2] + b0);
                gbuf[(mrow + gq + 8) * 132 + c0 + 1] = gelu1(uC[nt][3] + b1);
            }
            // ---- down: dC += gelu(64x128) @ Wdown(128x128) ----
            {   int r = tid >> 5, c4 = (tid & 31) * 4;
                cpa16(&wsm[r * 136 + c4], &ffn_down_w[(size_t)g * 65536 + (size_t)(ch * 128 + r) * 128 + c4]);
                cpcommit();
            }
            for (int ks = 0; ks < 16; ks++) {
                cpwait0(); __syncthreads();
                if (ks + 1 < 16) {
                    int r = tid >> 5, c4 = (tid & 31) * 4;
                    cpa16(&wsm[((ks + 1) & 1) * 1088 + r * 136 + c4],
                          &ffn_down_w[(size_t)g * 65536 + (size_t)(ch * 128 + (ks + 1) * 8 + r) * 128 + c4]);
                    cpcommit();
                }
                const float* wb = wsm + (ks & 1) * 1088;
                unsigned A[4];
                A[0] = cvt_tf32(gbuf[(mrow + gq) * 132 + ks * 8 + tig]);
                A[1] = cvt_tf32(gbuf[(mrow + gq + 8) * 132 + ks * 8 + tig]);
                A[2] = cvt_tf32(gbuf[(mrow + gq) * 132 + ks * 8 + tig + 4]);
                A[3] = cvt_tf32(gbuf[(mrow + gq + 8) * 132 + ks * 8 + tig + 4]);
#pragma unroll
                for (int nt = 0; nt < 8; nt++) {
                    unsigned b0 = __float_as_uint(wb[tig * 136 + ncol + nt * 8 + gq]);
                    unsigned b1 = __float_as_uint(wb[(tig + 4) * 136 + ncol + nt * 8 + gq]);
                    mma_tf32(dC[nt], A, b0, b1);
                }
            }
            __syncthreads();
        }

        // ===== x_out from dC frags =====
#pragma unroll
        for (int nt = 0; nt < 8; nt++) {
            int c0 = ncol + nt * 8 + 2 * tig;
            float b0 = ffn_down_b[g * 128 + c0];
            float b1 = ffn_down_b[g * 128 + c0 + 1];
            int r0 = mrow + gq, r1 = mrow + gq + 8;
            float2 x0 = *(float2*)&xs[r0 * 132 + c0];
            float2 x1 = *(float2*)&xs[r1 * 132 + c0];
            x0.x += dC[nt][0] + b0; x0.y += dC[nt][1] + b1;
            x1.x += dC[nt][2] + b0; x1.y += dC[nt][3] + b1;
            *(float2*)&xs[r0 * 132 + c0] = x0;
            *(float2*)&xs[r1 * 132 + c0] = x1;
            *(float2*)&out[O_XOUT + ((size_t)(t0 + r0) * Gn + g) * 128 + c0] = x0;
            *(float2*)&out[O_XOUT + ((size_t)(t0 + r1) * Gn + g) * 128 + c0] = x1;
        }
    }
    __syncthreads();

    // ================= post projection: two 128-wide passes =================
    for (int ph = 0; ph < 2; ph++) {
        U64 c2[4][4]; fz2(&c2[0][0], 16);
        gemm128u(xs, 132, post_w + (size_t)g * 32896 + ph * 128, 257, 128, wsm, c2, ty, tx, tid);
        long long voff = ph ? O_VC : O_VP;
        long long noff = ph ? O_QN : O_KC;
#pragma unroll
        for (int tt = 0; tt < 4; tt++) {
            size_t tg = t0 + ty * 4 + tt;
            float o0[4], o1[4]; up2(&c2[tt][0], o0); up2(&c2[tt][2], o1);
#pragma unroll
            for (int j = 0; j < 4; j++)
                bB[(ty * 4 + tt) * 136 + tx * 4 + j] =
                    o0[j] + post_b[(size_t)g * 257 + ph * 128 + tx * 4 + j];
            float4 v;
            v.x = o1[0] + post_b[(size_t)g * 257 + ph * 128 + 64 + tx * 4 + 0];
            v.y = o1[1] + post_b[(size_t)g * 257 + ph * 128 + 64 + tx * 4 + 1];
            v.z = o1[2] + post_b[(size_t)g * 257 + ph * 128 + 64 + tx * 4 + 2];
            v.w = o1[3] + post_b[(size_t)g * 257 + ph * 128 + 64 + tx * 4 + 3];
            *(float4*)&out[voff + (tg * Gn + g) * 64 + tx * 4] = v;
        }
        __syncthreads();
        {
            float4 r4[4];
            float ss = 0.f;
#pragma unroll
            for (int u4 = 0; u4 < 4; u4++) {
                r4[u4] = *(const float4*)&bB[tok * 136 + jq * 16 + u4 * 4];
                ss += r4[u4].x * r4[u4].x + r4[u4].y * r4[u4].y
                    + r4[u4].z * r4[u4].z + r4[u4].w * r4[u4].w;
            }
            ss += __shfl_xor_sync(0xffffffffu, ss, 1);
            ss += __shfl_xor_sync(0xffffffffu, ss, 2);
            float inv = 1.f / (sqrtf(ss) + 1e-6f);
            size_t tg = t0 + tok;
#pragma unroll
            for (int u4 = 0; u4 < 4; u4++) {
                float4 v;
                v.x = r4[u4].x * inv; v.y = r4[u4].y * inv;
                v.z = r4[u4].z * inv; v.w = r4[u4].w * inv;
                *(float4*)&out[noff + (tg * Gn + g) * 64 + jq * 16 + u4 * 4] = v;
            }
        }
        __syncthreads();
    }

    // ================= w_nov (proj column 256) =================
    if (tid < 128)
        wsm[tid] = post_w[(size_t)g * 32896 + (size_t)tid * 257 + 256];
    __syncthreads();
    {
        float acc = 0.f;
#pragma unroll
        for (int u = 0; u < 8; u++) {
            float4 xv = *(const float4*)&xs[tok * 132 + jq * 32 + u * 4];
            float4 wv = *(const float4*)&wsm[jq * 32 + u * 4];
            acc += xv.x * wv.x + xv.y * wv.y + xv.z * wv.z + xv.w * wv.w;
        }
        acc += __shfl_xor_sync(0xffffffffu, acc, 1);
        acc += __shfl_xor_sync(0xffffffffu, acc, 2);
        if (jq == 0) {
            size_t tg = t0 + tok;
            float nv = acc + post_b[(size_t)g * 257 + 256];
            out[O_WN + tg * Gn + g] = 1.f / (1.f + expf(-nv));
        }
    }
}

extern "C" void kernel_launch(void* const* d_in, const int* in_sizes, int n_in,
                              void* d_out, int out_size) {
    const float* x_col      = (const float*)d_in[0];
    const float* pm_state   = (const float*)d_in[1];
    const float* em_state   = (const float*)d_in[2];
    const float* z_hat_prev = (const float*)d_in[3];
    const float* ffn_norm_w = (const float*)d_in[4];
    const float* ffn_norm_b = (const float*)d_in[5];
    const float* ffn_up_w   = (const float*)d_in[6];
    const float* ffn_up_b   = (const float*)d_in[7];
    const float* ffn_down_w = (const float*)d_in[8];
    const float* ffn_down_b = (const float*)d_in[9];
    const float* pm_up_w    = (const float*)d_in[10];
    const float* pm_up_b    = (const float*)d_in[11];
    const float* pm_down_w  = (const float*)d_in[12];
    const float* pm_down_b  = (const float*)d_in[13];
    const float* em_up_w    = (const float*)d_in[14];
    const float* em_up_b    = (const float*)d_in[15];
    const float* em_down_w  = (const float*)d_in[16];
    const float* em_down_b  = (const float*)d_in[17];
    const float* post_w     = (const float*)d_in[18];
    const float* post_b     = (const float*)d_in[19];
    const float* enc_w      = (const float*)d_in[20];
    const float* enc_b      = (const float*)d_in[21];
    const float* pred_w     = (const float*)d_in[22];
    const float* pred_b     = (const float*)d_in[23];
    const float* gain_w     = (const float*)d_in[24];
    const float* gain_b     = (const float*)d_in[25];
    float* out = (float*)d_out;

    const int smem = (64 * 132 * 2 + 64 * 136 + 2 * 1088) * 4;  // 111104 B
    cudaFuncSetAttribute(ccg_kernel, cudaFuncAttributeMaxDynamicSharedMemorySize, smem);
    dim3 grid(32, 128);
    ccg_kernel<<<grid, 256, smem>>>(
        x_col, pm_state, em_state, z_hat_prev,
        ffn_norm_w, ffn_norm_b, ffn_up_w, ffn_up_b, ffn_down_w, ffn_down_b,
        pm_up_w, pm_up_b, pm_down_w, pm_down_b,
        em_up_w, em_up_b, em_down_w, em_down_b,
        post_w, post_b, enc_w, enc_b, pred_w, pred_b, gain_w, gain_b,
        out);
}

// round 16
// speedup vs baseline: 1.6438x; 1.1010x over previous
#include <cuda_runtime.h>
#include <math.h>

#define Gn 128
typedef unsigned long long U64;

static const long long O_XOUT = 0LL;
static const long long O_Z    = 33554432LL;
static const long long O_ZHAT = 50331648LL;
static const long long O_SURP = 67108864LL;
static const long long O_KC   = 67371008LL;
static const long long O_VP   = 84148224LL;
static const long long O_GATE = 100925440LL;
static const long long O_QN   = 101187584LL;
static const long long O_VC   = 117964800LL;
static const long long O_WN   = 134742016LL;
static const long long O_S4   = 135004160LL;

__device__ __forceinline__ void f2fma(U64& d, U64 a, U64 b) {
    asm("fma.rn.f32x2 %0, %1, %2, %0;" : "+l"(d) : "l"(a), "l"(b));
}
__device__ __forceinline__ U64 dup2(float a) {
    U64 r; asm("mov.b64 %0, {%1, %1};" : "=l"(r) : "f"(a)); return r;
}
__device__ __forceinline__ float2 unpk(U64 v) {
    float2 f; asm("mov.b64 {%0, %1}, %2;" : "=f"(f.x), "=f"(f.y) : "l"(v)); return f;
}
__device__ __forceinline__ void cpa16(float* dst, const float* src) {
    unsigned d = (unsigned)__cvta_generic_to_shared(dst);
    asm volatile("cp.async.ca.shared.global [%0], [%1], 16;" :: "r"(d), "l"(src) : "memory");
}
__device__ __forceinline__ void cpa4(float* dst, const float* src) {
    unsigned d = (unsigned)__cvta_generic_to_shared(dst);
    asm volatile("cp.async.ca.shared.global [%0], [%1], 4;" :: "r"(d), "l"(src) : "memory");
}
__device__ __forceinline__ void cpcommit() { asm volatile("cp.async.commit_group;" ::: "memory"); }
__device__ __forceinline__ void cpwait0()  { asm volatile("cp.async.wait_group 0;" ::: "memory"); }

__device__ __forceinline__ void mma_tf32(float* d, const unsigned* a, unsigned b0, unsigned b1) {
    asm volatile("mma.sync.aligned.m16n8k8.row.col.f32.tf32.tf32.f32 "
        "{%0,%1,%2,%3}, {%4,%5,%6,%7}, {%8,%9}, {%0,%1,%2,%3};"
        : "+f"(d[0]), "+f"(d[1]), "+f"(d[2]), "+f"(d[3])
        : "r"(a[0]), "r"(a[1]), "r"(a[2]), "r"(a[3]), "r"(b0), "r"(b1));
}
__device__ __forceinline__ unsigned cvt_tf32(float f) {
    unsigned u; asm("cvt.rna.tf32.f32 %0, %1;" : "=r"(u) : "f"(f)); return u;
}
__device__ __forceinline__ float gelu1(float u) {
    return 0.5f * u * (1.f + erff(u * 0.70710678f));
}
__device__ __forceinline__ void fdz(float d[8][4]) {
#pragma unroll
    for (int i = 0; i < 8; i++)
#pragma unroll
        for (int j = 0; j < 4; j++) d[i][j] = 0.f;
}

// Generic tf32 MMA GEMM: dC += A(64xK, smem stride sas) @ W(K x 128)
// warps: wid&3 = 16-row band, wid>>2 = 64-col half. UA: 4B-aligned weight rows.
template<bool UA>
__device__ __forceinline__ void mmaG(const float* As, int sas,
    const float* __restrict__ W, long wst, int K,
    float* wsm, float dC[8][4], int tid)
{
    int nk = K >> 3;
    const int lane = tid & 31, wid = tid >> 5;
    const int gq = lane >> 2, tig = lane & 3;
    const int mrow = (wid & 3) * 16, ncol = (wid >> 2) * 64;
#define STG(k0, buf) do{ \
    if (UA){ for (int j = 0; j < 4; j++){ int flat = tid + 256*j; int r_ = flat>>7, col_ = flat&127; \
        cpa4(&(buf)[r_*136 + col_], &W[(size_t)((k0)+r_)*wst + col_]); } } \
    else { int r_ = tid>>5, c4_ = (tid&31)*4; \
        cpa16(&(buf)[r_*136 + c4_], &W[(size_t)((k0)+r_)*wst + c4_]); } \
    cpcommit(); } while(0)
    STG(0, wsm);
    for (int ks = 0; ks < nk; ks++) {
        cpwait0(); __syncthreads();
        if (ks + 1 < nk) STG((ks + 1) * 8, wsm + ((ks + 1) & 1) * 1088);
        const float* wb = wsm + (ks & 1) * 1088;
        unsigned A[4];
        A[0] = cvt_tf32(As[(mrow + gq) * sas + ks * 8 + tig]);
        A[1] = cvt_tf32(As[(mrow + gq + 8) * sas + ks * 8 + tig]);
        A[2] = cvt_tf32(As[(mrow + gq) * sas + ks * 8 + tig + 4]);
        A[3] = cvt_tf32(As[(mrow + gq + 8) * sas + ks * 8 + tig + 4]);
#pragma unroll
        for (int nt = 0; nt < 8; nt++) {
            unsigned b0 = __float_as_uint(wb[tig * 136 + ncol + nt * 8 + gq]);
            unsigned b1 = __float_as_uint(wb[(tig + 4) * 136 + ncol + nt * 8 + gq]);
            mma_tf32(dC[nt], A, b0, b1);
        }
    }
    __syncthreads();
#undef STG
}

// epilogue: xs += dC + bias
__device__ __forceinline__ void epAddXs(float dC[8][4], float* xs,
                                        const float* __restrict__ bias, int tid) {
    const int lane = tid & 31, wid = tid >> 5;
    const int gq = lane >> 2, tig = lane & 3;
    const int mrow = (wid & 3) * 16, ncol = (wid >> 2) * 64;
#pragma unroll
    for (int nt = 0; nt < 8; nt++) {
        int c0 = ncol + nt * 8 + 2 * tig;
        float b0 = bias[c0], b1 = bias[c0 + 1];
        float2* p0 = (float2*)&xs[(mrow + gq) * 132 + c0];
        float2* p1 = (float2*)&xs[(mrow + gq + 8) * 132 + c0];
        float2 v0 = *p0, v1 = *p1;
        v0.x += dC[nt][0] + b0; v0.y += dC[nt][1] + b1;
        v1.x += dC[nt][2] + b0; v1.y += dC[nt][3] + b1;
        *p0 = v0; *p1 = v1;
    }
}

// ---------- FFMA staging + cores (64-wide only) ----------
__device__ __forceinline__ void st64(const float* __restrict__ W, long wst, int k0,
                                     float* buf, int tid) {
    int r = tid >> 4, cc = tid & 15;
    cpa16(&buf[r * 68 + cc * 4], &W[(size_t)(k0 + r) * wst + cc * 4]);
    cpcommit();
}
__device__ __forceinline__ void inner64(const float* __restrict__ As, int sas, int k0,
                                        const float* wb, U64 c2[][2], int ty, int tx) {
#pragma unroll
    for (int i4 = 0; i4 < 4; i4++) {
        float4 a4[4];
#pragma unroll
        for (int tt = 0; tt < 4; tt++)
            a4[tt] = *(const float4*)&As[(ty * 4 + tt) * sas + k0 + i4 * 4];
#pragma unroll
        for (int ii = 0; ii < 4; ii++) {
            ulonglong2 w = *(const ulonglong2*)&wb[(i4 * 4 + ii) * 68 + tx * 4];
#pragma unroll
            for (int tt = 0; tt < 4; tt++) {
                U64 a = dup2(((const float*)&a4[tt])[ii]);
                f2fma(c2[tt][0], a, w.x);
                f2fma(c2[tt][1], a, w.y);
            }
        }
    }
}
__device__ __forceinline__ void gemm64(const float* __restrict__ As, int sas,
                                       const float* __restrict__ W, long wst, int K,
                                       float* wsm, U64 c2[][2], int ty, int tx, int tid) {
    int nc = K >> 4;
    st64(W, wst, 0, wsm, tid);
    for (int c = 0; c < nc; c++) {
        cpwait0();
        __syncthreads();
        if (c + 1 < nc) st64(W, wst, (c + 1) << 4, wsm + ((c + 1) & 1) * 1088, tid);
        inner64(As, sas, c << 4, wsm + (c & 1) * 1088, c2, ty, tx);
    }
    __syncthreads();
}
__device__ __forceinline__ void gemm64T(const float* __restrict__ As, int sas,
                                        const float* __restrict__ S, int slots, int K,
                                        float* wsm, U64 c2[][2], int ty, int tx, int tid) {
    for (int k0 = 0; k0 < K; k0 += 16) {
        int s = tid & 63, k4 = tid >> 6;
        float4 v = make_float4(0.f, 0.f, 0.f, 0.f);
        if (s < slots) v = *(const float4*)&S[s * 64 + k0 + k4 * 4];
        __syncthreads();
        wsm[(k4 * 4 + 0) * 68 + s] = v.x;
        wsm[(k4 * 4 + 1) * 68 + s] = v.y;
        wsm[(k4 * 4 + 2) * 68 + s] = v.z;
        wsm[(k4 * 4 + 3) * 68 + s] = v.w;
        __syncthreads();
        inner64(As, sas, k0, wsm, c2, ty, tx);
    }
    __syncthreads();
}
__device__ __forceinline__ void fz2(U64* c, int n) {
    for (int i = 0; i < n; i++) c[i] = 0ULL;
}
__device__ __forceinline__ void up2(const U64* c2, float* o) {
    float2 a = unpk(c2[0]), b = unpk(c2[1]);
    o[0] = a.x; o[1] = a.y; o[2] = b.x; o[3] = b.y;
}
template <int SLOTS>
__device__ __forceinline__ void softmax_q(float* buf, int tok, int jq) {
    const int nS = SLOTS / 4;
    float l[nS];
    float m = -1e30f;
#pragma unroll
    for (int i = 0; i < nS; i++) {
        l[i] = buf[tok * 136 + jq * nS + i] * 0.125f;
        m = fmaxf(m, l[i]);
    }
    m = fmaxf(m, __shfl_xor_sync(0xffffffffu, m, 1));
    m = fmaxf(m, __shfl_xor_sync(0xffffffffu, m, 2));
    float s = 0.f;
#pragma unroll
    for (int i = 0; i < nS; i++) { l[i] = expf(l[i] - m); s += l[i]; }
    s += __shfl_xor_sync(0xffffffffu, s, 1);
    s += __shfl_xor_sync(0xffffffffu, s, 2);
    float inv = 1.f / s;
#pragma unroll
    for (int i = 0; i < nS; i++) buf[tok * 136 + jq * nS + i] = l[i] * inv;
}

__global__ void __launch_bounds__(256, 2)
ccg_kernel(
    const float* __restrict__ x_col, const float* __restrict__ pm_state,
    const float* __restrict__ em_state, const float* __restrict__ z_hat_prev,
    const float* __restrict__ ffn_norm_w, const float* __restrict__ ffn_norm_b,
    const float* __restrict__ ffn_up_w, const float* __restrict__ ffn_up_b,
    const float* __restrict__ ffn_down_w, const float* __restrict__ ffn_down_b,
    const float* __restrict__ pm_up_w, const float* __restrict__ pm_up_b,
    const float* __restrict__ pm_down_w, const float* __restrict__ pm_down_b,
    const float* __restrict__ em_up_w, const float* __restrict__ em_up_b,
    const float* __restrict__ em_down_w, const float* __restrict__ em_down_b,
    const float* __restrict__ post_w, const float* __restrict__ post_b,
    const float* __restrict__ enc_w, const float* __restrict__ enc_b,
    const float* __restrict__ pred_w, const float* __restrict__ pred_b,
    const float* __restrict__ gain_w, const float* __restrict__ gain_b,
    float* __restrict__ out)
{
    extern __shared__ float smf[];
    float* xs  = smf;                 // 64 x 132
    float* hs  = xs + 64 * 132;       // 64 x 132
    float* bA  = hs + 64 * 132;       // 64 x 136 (cols 0..67), gelu buf stride 132
    float* bB  = bA + 68;             //             (cols 68..135)
    float* wsm = bA + 64 * 136;       // 2 x 1088 weight staging

    const int tid = threadIdx.x;
    const int ty = tid >> 4, tx = tid & 15;
    const int tok = tid >> 2, jq = tid & 3;
    const int g  = blockIdx.y;
    const int t0 = blockIdx.x * 64;
    const int bs = t0 >> 9;
    const int bidx = g >> 4;

#pragma unroll
    for (int jj = 0; jj < 8; jj++) {
        int flat = tid + 256 * jj;
        int r = flat >> 5, c4 = flat & 31;
        *(float4*)&xs[r * 132 + c4 * 4] =
            *(const float4*)&x_col[((size_t)(t0 + r) * Gn + g) * 128 + c4 * 4];
    }

    // ================= pm memory stage =================
    {
        U64 c2[4][2]; fz2(&c2[0][0], 8);
        gemm64(xs, 132, pm_up_w + (size_t)g * 8192, 64, 128, wsm, c2, ty, tx, tid);
#pragma unroll
        for (int tt = 0; tt < 4; tt++) {
            float o[4]; up2(c2[tt], o);
#pragma unroll
            for (int j = 0; j < 4; j++)
                bB[(ty * 4 + tt) * 136 + tx * 4 + j] = o[j] + pm_up_b[g * 64 + tx * 4 + j];
        }
    }
    const float* Spm = pm_state + (size_t)((bs * 8 + bidx) * 16) * 64;
    {
        U64 c2[4][2]; fz2(&c2[0][0], 8);
        gemm64T(bB, 136, Spm, 16, 64, wsm, c2, ty, tx, tid);
        if (tx < 4) {
#pragma unroll
            for (int tt = 0; tt < 4; tt++) {
                float o[4]; up2(c2[tt], o);
#pragma unroll
                for (int j = 0; j < 4; j++) bA[(ty * 4 + tt) * 136 + tx * 4 + j] = o[j];
            }
        }
    }
    __syncthreads();
    softmax_q<16>(bA, tok, jq);
    __syncthreads();
    {
        U64 c2[4][2]; fz2(&c2[0][0], 8);
        gemm64(bA, 136, Spm, 64, 16, wsm, c2, ty, tx, tid);
#pragma unroll
        for (int tt = 0; tt < 4; tt++) {
            float o[4]; up2(c2[tt], o);
#pragma unroll
            for (int j = 0; j < 4; j++) bB[(ty * 4 + tt) * 136 + tx * 4 + j] = o[j];
        }
    }
    __syncthreads();
    {
        float dC[8][4]; fdz(dC);
        mmaG<false>(bB, 136, pm_down_w + (size_t)g * 8192, 128, 64, wsm, dC, tid);
        epAddXs(dC, xs, pm_down_b + g * 128, tid);
    }
    __syncthreads();

    // ================= em memory stage =================
    {
        U64 c2[4][2]; fz2(&c2[0][0], 8);
        gemm64(xs, 132, em_up_w + (size_t)g * 8192, 64, 128, wsm, c2, ty, tx, tid);
#pragma unroll
        for (int tt = 0; tt < 4; tt++) {
            float o[4]; up2(c2[tt], o);
#pragma unroll
            for (int j = 0; j < 4; j++)
                bB[(ty * 4 + tt) * 136 + tx * 4 + j] = o[j] + em_up_b[g * 64 + tx * 4 + j];
        }
    }
    const float* Sem = em_state + (size_t)((bs * 8 + bidx) * 64) * 64;
    {
        U64 c2[4][2]; fz2(&c2[0][0], 8);
        gemm64T(bB, 136, Sem, 64, 64, wsm, c2, ty, tx, tid);
#pragma unroll
        for (int tt = 0; tt < 4; tt++) {
            float o[4]; up2(c2[tt], o);
#pragma unroll
            for (int j = 0; j < 4; j++) bA[(ty * 4 + tt) * 136 + tx * 4 + j] = o[j];
        }
    }
    __syncthreads();
    softmax_q<64>(bA, tok, jq);
    __syncthreads();
    {
        U64 c2[4][2]; fz2(&c2[0][0], 8);
        gemm64(bA, 136, Sem, 64, 64, wsm, c2, ty, tx, tid);
#pragma unroll
        for (int tt = 0; tt < 4; tt++) {
            float o[4]; up2(c2[tt], o);
#pragma unroll
            for (int j = 0; j < 4; j++) bB[(ty * 4 + tt) * 136 + tx * 4 + j] = o[j];
        }
    }
    __syncthreads();
    {
        float dC[8][4]; fdz(dC);
        mmaG<false>(bB, 136, em_down_w + (size_t)g * 8192, 128, 64, wsm, dC, tid);
        epAddXs(dC, xs, em_down_b + g * 128, tid);
    }
    __syncthreads();

    // ================= enc / delta / surprise (FFMA, precision-critical) =================
    {
        U64 c2[4][2]; fz2(&c2[0][0], 8);
        gemm64(xs, 132, enc_w + (size_t)g * 8192, 64, 128, wsm, c2, ty, tx, tid);
        float sp[4];
#pragma unroll
        for (int tt = 0; tt < 4; tt++) {
            int t = ty * 4 + tt;
            size_t tg = t0 + t;
            float o[4]; up2(c2[tt], o);
            float4 zh4 = *(const float4*)&z_hat_prev[(tg * Gn + g) * 64 + tx * 4];
            float z0 = o[0] + enc_b[g * 64 + tx * 4 + 0];
            float z1 = o[1] + enc_b[g * 64 + tx * 4 + 1];
            float z2 = o[2] + enc_b[g * 64 + tx * 4 + 2];
            float z3 = o[3] + enc_b[g * 64 + tx * 4 + 3];
            bA[t * 136 + tx * 4 + 0] = z0; bA[t * 136 + tx * 4 + 1] = z1;
            bA[t * 136 + tx * 4 + 2] = z2; bA[t * 136 + tx * 4 + 3] = z3;
            float e0 = z0 - zh4.x, e1 = z1 - zh4.y, e2 = z2 - zh4.z, e3 = z3 - zh4.w;
            bB[t * 136 + tx * 4 + 0] = e0; bB[t * 136 + tx * 4 + 1] = e1;
            bB[t * 136 + tx * 4 + 2] = e2; bB[t * 136 + tx * 4 + 3] = e3;
            sp[tt] = e0 * e0 + e1 * e1 + e2 * e2 + e3 * e3;
            *(float4*)&out[O_Z + (tg * Gn + g) * 64 + tx * 4] = make_float4(z0, z1, z2, z3);
        }
#pragma unroll
        for (int tt = 0; tt < 4; tt++) {
            sp[tt] += __shfl_xor_sync(0xffffffffu, sp[tt], 1);
            sp[tt] += __shfl_xor_sync(0xffffffffu, sp[tt], 2);
            sp[tt] += __shfl_xor_sync(0xffffffffu, sp[tt], 4);
            sp[tt] += __shfl_xor_sync(0xffffffffu, sp[tt], 8);
        }
        if (tx == 0) {
#pragma unroll
            for (int tt = 0; tt < 4; tt++) {
                size_t tg = t0 + ty * 4 + tt;
                float s = sqrtf(sp[tt]);
                out[O_SURP + tg * Gn + g] = s;
                out[O_S4 + tg * Gn + g] = s;
                out[O_GATE + tg * Gn + g] = fminf(s, 1.f);
            }
        }
    }
    __syncthreads();

    // ================= gain (delta in bB) via MMA -> hs =================
    {
        float dC[8][4]; fdz(dC);
        mmaG<false>(bB, 136, gain_w + (size_t)g * 8192, 128, 64, wsm, dC, tid);
        const int lane = tid & 31, wid = tid >> 5;
        const int gq = lane >> 2, tig = lane & 3;
        const int mrow = (wid & 3) * 16, ncol = (wid >> 2) * 64;
#pragma unroll
        for (int nt = 0; nt < 8; nt++) {
            int c0 = ncol + nt * 8 + 2 * tig;
            float b0 = gain_b[g * 128 + c0], b1 = gain_b[g * 128 + c0 + 1];
            hs[(mrow + gq) * 132 + c0]     = 1.f + 0.1f * tanhf(dC[nt][0] + b0);
            hs[(mrow + gq) * 132 + c0 + 1] = 1.f + 0.1f * tanhf(dC[nt][1] + b1);
            hs[(mrow + gq + 8) * 132 + c0]     = 1.f + 0.1f * tanhf(dC[nt][2] + b0);
            hs[(mrow + gq + 8) * 132 + c0 + 1] = 1.f + 0.1f * tanhf(dC[nt][3] + b1);
        }
    }

    // ================= z_hat (z in bA, FFMA) =================
    {
        U64 c2[4][2]; fz2(&c2[0][0], 8);
        gemm64(bA, 136, pred_w + (size_t)g * 4096, 64, 64, wsm, c2, ty, tx, tid);
#pragma unroll
        for (int tt = 0; tt < 4; tt++) {
            size_t tg = t0 + ty * 4 + tt;
            float o[4]; up2(c2[tt], o);
            float4 v;
            v.x = o[0] + pred_b[g * 64 + tx * 4 + 0];
            v.y = o[1] + pred_b[g * 64 + tx * 4 + 1];
            v.z = o[2] + pred_b[g * 64 + tx * 4 + 2];
            v.w = o[3] + pred_b[g * 64 + tx * 4 + 3];
            *(float4*)&out[O_ZHAT + (tg * Gn + g) * 64 + tx * 4] = v;
        }
    }
    __syncthreads();

    // ================= layernorm * gain -> hs =================
    {
        float s = 0.f, sq = 0.f;
        float4 xv[8];
#pragma unroll
        for (int u = 0; u < 8; u++) {
            xv[u] = *(const float4*)&xs[tok * 132 + jq * 32 + u * 4];
            s  += xv[u].x + xv[u].y + xv[u].z + xv[u].w;
            sq += xv[u].x * xv[u].x + xv[u].y * xv[u].y + xv[u].z * xv[u].z + xv[u].w * xv[u].w;
        }
        s  += __shfl_xor_sync(0xffffffffu, s, 1);
        s  += __shfl_xor_sync(0xffffffffu, s, 2);
        sq += __shfl_xor_sync(0xffffffffu, sq, 1);
        sq += __shfl_xor_sync(0xffffffffu, sq, 2);
        float mu = s * (1.f / 128.f);
        float rstd = rsqrtf(sq * (1.f / 128.f) - mu * mu + 1e-5f);
#pragma unroll
        for (int u = 0; u < 8; u++) {
            int cb = jq * 32 + u * 4;
            float4 w4 = *(const float4*)&ffn_norm_w[g * 128 + cb];
            float4 b4 = *(const float4*)&ffn_norm_b[g * 128 + cb];
            float4 g4 = *(const float4*)&hs[tok * 132 + cb];
            float4 h4;
            h4.x = ((xv[u].x - mu) * rstd * w4.x + b4.x) * g4.x;
            h4.y = ((xv[u].y - mu) * rstd * w4.y + b4.y) * g4.y;
            h4.z = ((xv[u].z - mu) * rstd * w4.z + b4.z) * g4.z;
            h4.w = ((xv[u].w - mu) * rstd * w4.w + b4.w) * g4.w;
            *(float4*)&hs[tok * 132 + cb] = h4;
        }
    }

    // ================= FFN via tf32 tensor cores =================
    {
        const int wid = tid >> 5, lane = tid & 31;
        const int gq = lane >> 2, tig = lane & 3;
        const int mrow = (wid & 3) * 16;
        const int ncol = (wid >> 2) * 64;
        float* gbuf = bA;

        float dC[8][4]; fdz(dC);

        for (int ch = 0; ch < 4; ch++) {
            float uC[8][4]; fdz(uC);
            {   int r = tid >> 5, c4 = (tid & 31) * 4;
                cpa16(&wsm[r * 136 + c4], &ffn_up_w[(size_t)g * 65536 + (size_t)r * 512 + ch * 128 + c4]);
                cpcommit();
            }
            for (int ks = 0; ks < 16; ks++) {
                cpwait0(); __syncthreads();
                if (ks + 1 < 16) {
                    int r = tid >> 5, c4 = (tid & 31) * 4;
                    cpa16(&wsm[((ks + 1) & 1) * 1088 + r * 136 + c4],
                          &ffn_up_w[(size_t)g * 65536 + (size_t)((ks + 1) * 8 + r) * 512 + ch * 128 + c4]);
                    cpcommit();
                }
                const float* wb = wsm + (ks & 1) * 1088;
                unsigned A[4];
                A[0] = cvt_tf32(hs[(mrow + gq) * 132 + ks * 8 + tig]);
                A[1] = cvt_tf32(hs[(mrow + gq + 8) * 132 + ks * 8 + tig]);
                A[2] = cvt_tf32(hs[(mrow + gq) * 132 + ks * 8 + tig + 4]);
                A[3] = cvt_tf32(hs[(mrow + gq + 8) * 132 + ks * 8 + tig + 4]);
#pragma unroll
                for (int nt = 0; nt < 8; nt++) {
                    unsigned b0 = __float_as_uint(wb[tig * 136 + ncol + nt * 8 + gq]);
                    unsigned b1 = __float_as_uint(wb[(tig + 4) * 136 + ncol + nt * 8 + gq]);
                    mma_tf32(uC[nt], A, b0, b1);
                }
            }
            __syncthreads();
#pragma unroll
            for (int nt = 0; nt < 8; nt++) {
                int c0 = ncol + nt * 8 + 2 * tig;
                float b0 = ffn_up_b[g * 512 + ch * 128 + c0];
                float b1 = ffn_up_b[g * 512 + ch * 128 + c0 + 1];
                gbuf[(mrow + gq) * 132 + c0]     = gelu1(uC[nt][0] + b0);
                gbuf[(mrow + gq) * 132 + c0 + 1] = gelu1(uC[nt][1] + b1);
                gbuf[(mrow + gq + 8) * 132 + c0]     = gelu1(uC[nt][2] + b0);
                gbuf[(mrow + gq + 8) * 132 + c0 + 1] = gelu1(uC[nt][3] + b1);
            }
            {   int r = tid >> 5, c4 = (tid & 31) * 4;
                cpa16(&wsm[r * 136 + c4], &ffn_down_w[(size_t)g * 65536 + (size_t)(ch * 128 + r) * 128 + c4]);
                cpcommit();
            }
            for (int ks = 0; ks < 16; ks++) {
                cpwait0(); __syncthreads();
                if (ks + 1 < 16) {
                    int r = tid >> 5, c4 = (tid & 31) * 4;
                    cpa16(&wsm[((ks + 1) & 1) * 1088 + r * 136 + c4],
                          &ffn_down_w[(size_t)g * 65536 + (size_t)(ch * 128 + (ks + 1) * 8 + r) * 128 + c4]);
                    cpcommit();
                }
                const float* wb = wsm + (ks & 1) * 1088;
                unsigned A[4];
                A[0] = cvt_tf32(gbuf[(mrow + gq) * 132 + ks * 8 + tig]);
                A[1] = cvt_tf32(gbuf[(mrow + gq + 8) * 132 + ks * 8 + tig]);
                A[2] = cvt_tf32(gbuf[(mrow + gq) * 132 + ks * 8 + tig + 4]);
                A[3] = cvt_tf32(gbuf[(mrow + gq + 8) * 132 + ks * 8 + tig + 4]);
#pragma unroll
                for (int nt = 0; nt < 8; nt++) {
                    unsigned b0 = __float_as_uint(wb[tig * 136 + ncol + nt * 8 + gq]);
                    unsigned b1 = __float_as_uint(wb[(tig + 4) * 136 + ncol + nt * 8 + gq]);
                    mma_tf32(dC[nt], A, b0, b1);
                }
            }
            __syncthreads();
        }

#pragma unroll
        for (int nt = 0; nt < 8; nt++) {
            int c0 = ncol + nt * 8 + 2 * tig;
            float b0 = ffn_down_b[g * 128 + c0];
            float b1 = ffn_down_b[g * 128 + c0 + 1];
            int r0 = mrow + gq, r1 = mrow + gq + 8;
            float2 x0 = *(float2*)&xs[r0 * 132 + c0];
            float2 x1 = *(float2*)&xs[r1 * 132 + c0];
            x0.x += dC[nt][0] + b0; x0.y += dC[nt][1] + b1;
            x1.x += dC[nt][2] + b0; x1.y += dC[nt][3] + b1;
            *(float2*)&xs[r0 * 132 + c0] = x0;
            *(float2*)&xs[r1 * 132 + c0] = x1;
            *(float2*)&out[O_XOUT + ((size_t)(t0 + r0) * Gn + g) * 128 + c0] = x0;
            *(float2*)&out[O_XOUT + ((size_t)(t0 + r1) * Gn + g) * 128 + c0] = x1;
        }
    }
    __syncthreads();

    // ================= post projection via MMA (two 128-wide passes) =================
    for (int ph = 0; ph < 2; ph++) {
        float dC[8][4]; fdz(dC);
        mmaG<true>(xs, 132, post_w + (size_t)g * 32896 + ph * 128, 257, 128, wsm, dC, tid);
        long long voff = ph ? O_VC : O_VP;
        long long noff = ph ? O_QN : O_KC;
        {
            const int lane = tid & 31, wid = tid >> 5;
            const int gq = lane >> 2, tig = lane & 3;
            const int mrow = (wid & 3) * 16, ncol = (wid >> 2) * 64;
#pragma unroll
            for (int nt = 0; nt < 8; nt++) {
                int c0 = ncol + nt * 8 + 2 * tig;
                float b0 = post_b[(size_t)g * 257 + ph * 128 + c0];
                float b1 = post_b[(size_t)g * 257 + ph * 128 + c0 + 1];
                float v00 = dC[nt][0] + b0, v01 = dC[nt][1] + b1;
                float v10 = dC[nt][2] + b0, v11 = dC[nt][3] + b1;
                int r0 = mrow + gq, r1 = mrow + gq + 8;
                if (ncol == 0) {
                    *(float2*)&bB[r0 * 136 + c0] = make_float2(v00, v01);
                    *(float2*)&bB[r1 * 136 + c0] = make_float2(v10, v11);
                } else {
                    int cc = c0 - 64;
                    *(float2*)&out[voff + ((size_t)(t0 + r0) * Gn + g) * 64 + cc] = make_float2(v00, v01);
                    *(float2*)&out[voff + ((size_t)(t0 + r1) * Gn + g) * 64 + cc] = make_float2(v10, v11);
                }
            }
        }
        __syncthreads();
        {
            float4 r4[4];
            float ss = 0.f;
#pragma unroll
            for (int u4 = 0; u4 < 4; u4++) {
                r4[u4] = *(const float4*)&bB[tok * 136 + jq * 16 + u4 * 4];
                ss += r4[u4].x * r4[u4].x + r4[u4].y * r4[u4].y
                    + r4[u4].z * r4[u4].z + r4[u4].w * r4[u4].w;
            }
            ss += __shfl_xor_sync(0xffffffffu, ss, 1);
            ss += __shfl_xor_sync(0xffffffffu, ss, 2);
            float inv = 1.f / (sqrtf(ss) + 1e-6f);
            size_t tg = t0 + tok;
#pragma unroll
            for (int u4 = 0; u4 < 4; u4++) {
                float4 v;
                v.x = r4[u4].x * inv; v.y = r4[u4].y * inv;
                v.z = r4[u4].z * inv; v.w = r4[u4].w * inv;
                *(float4*)&out[noff + (tg * Gn + g) * 64 + jq * 16 + u4 * 4] = v;
            }
        }
        __syncthreads();
    }

    // ================= w_nov (proj column 256) =================
    if (tid < 128)
        wsm[tid] = post_w[(size_t)g * 32896 + (size_t)tid * 257 + 256];
    __syncthreads();
    {
        float acc = 0.f;
#pragma unroll
        for (int u = 0; u < 8; u++) {
            float4 xv = *(const float4*)&xs[tok * 132 + jq * 32 + u * 4];
            float4 wv = *(const float4*)&wsm[jq * 32 + u * 4];
            acc += xv.x * wv.x + xv.y * wv.y + xv.z * wv.z + xv.w * wv.w;
        }
        acc += __shfl_xor_sync(0xffffffffu, acc, 1);
        acc += __shfl_xor_sync(0xffffffffu, acc, 2);
        if (jq == 0) {
            size_t tg = t0 + tok;
            float nv = acc + post_b[(size_t)g * 257 + 256];
            out[O_WN + tg * Gn + g] = 1.f / (1.f + expf(-nv));
        }
    }
}

extern "C" void kernel_launch(void* const* d_in, const int* in_sizes, int n_in,
                              void* d_out, int out_size) {
    const float* x_col      = (const float*)d_in[0];
    const float* pm_state   = (const float*)d_in[1];
    const float* em_state   = (const float*)d_in[2];
    const float* z_hat_prev = (const float*)d_in[3];
    const float* ffn_norm_w = (const float*)d_in[4];
    const float* ffn_norm_b = (const float*)d_in[5];
    const float* ffn_up_w   = (const float*)d_in[6];
    const float* ffn_up_b   = (const float*)d_in[7];
    const float* ffn_down_w = (const float*)d_in[8];
    const float* ffn_down_b = (const float*)d_in[9];
    const float* pm_up_w    = (const float*)d_in[10];
    const float* pm_up_b    = (const float*)d_in[11];
    const float* pm_down_w  = (const float*)d_in[12];
    const float* pm_down_b  = (const float*)d_in[13];
    const float* em_up_w    = (const float*)d_in[14];
    const float* em_up_b    = (const float*)d_in[15];
    const float* em_down_w  = (const float*)d_in[16];
    const float* em_down_b  = (const float*)d_in[17];
    const float* post_w     = (const float*)d_in[18];
    const float* post_b     = (const float*)d_in[19];
    const float* enc_w      = (const float*)d_in[20];
    const float* enc_b      = (const float*)d_in[21];
    const float* pred_w     = (const float*)d_in[22];
    const float* pred_b     = (const float*)d_in[23];
    const float* gain_w     = (const float*)d_in[24];
    const float* gain_b     = (const float*)d_in[25];
    float* out = (float*)d_out;

    const int smem = (64 * 132 * 2 + 64 * 136 + 2 * 1088) * 4;  // 111104 B
    cudaFuncSetAttribute(ccg_kernel, cudaFuncAttributeMaxDynamicSharedMemorySize, smem);
    dim3 grid(32, 128);
    ccg_kernel<<<grid, 256, smem>>>(
        x_col, pm_state, em_state, z_hat_prev,
        ffn_norm_w, ffn_norm_b, ffn_up_w, ffn_up_b, ffn_down_w, ffn_down_b,
        pm_up_w, pm_up_b, pm_down_w, pm_down_b,
        em_up_w, em_up_b, em_down_w, em_down_b,
        post_w, post_b, enc_w, enc_b, pred_w, pred_b, gain_w, gain_b,
        out);
}

// round 17
// speedup vs baseline: 1.6688x; 1.0152x over previous
#include <cuda_runtime.h>
#include <math.h>

#define Gn 128
typedef unsigned long long U64;

static const long long O_XOUT = 0LL;
static const long long O_Z    = 33554432LL;
static const long long O_ZHAT = 50331648LL;
static const long long O_SURP = 67108864LL;
static const long long O_KC   = 67371008LL;
static const long long O_VP   = 84148224LL;
static const long long O_GATE = 100925440LL;
static const long long O_QN   = 101187584LL;
static const long long O_VC   = 117964800LL;
static const long long O_WN   = 134742016LL;
static const long long O_S4   = 135004160LL;

__device__ __forceinline__ void f2fma(U64& d, U64 a, U64 b) {
    asm("fma.rn.f32x2 %0, %1, %2, %0;" : "+l"(d) : "l"(a), "l"(b));
}
__device__ __forceinline__ U64 dup2(float a) {
    U64 r; asm("mov.b64 %0, {%1, %1};" : "=l"(r) : "f"(a)); return r;
}
__device__ __forceinline__ float2 unpk(U64 v) {
    float2 f; asm("mov.b64 {%0, %1}, %2;" : "=f"(f.x), "=f"(f.y) : "l"(v)); return f;
}
__device__ __forceinline__ void cpa16(float* dst, const float* src) {
    unsigned d = (unsigned)__cvta_generic_to_shared(dst);
    asm volatile("cp.async.ca.shared.global [%0], [%1], 16;" :: "r"(d), "l"(src) : "memory");
}
__device__ __forceinline__ void cpa4(float* dst, const float* src) {
    unsigned d = (unsigned)__cvta_generic_to_shared(dst);
    asm volatile("cp.async.ca.shared.global [%0], [%1], 4;" :: "r"(d), "l"(src) : "memory");
}
__device__ __forceinline__ void cpcommit() { asm volatile("cp.async.commit_group;" ::: "memory"); }
__device__ __forceinline__ void cpwait0()  { asm volatile("cp.async.wait_group 0;" ::: "memory"); }

__device__ __forceinline__ void mma_tf32(float* d, const unsigned* a, unsigned b0, unsigned b1) {
    asm volatile("mma.sync.aligned.m16n8k8.row.col.f32.tf32.tf32.f32 "
        "{%0,%1,%2,%3}, {%4,%5,%6,%7}, {%8,%9}, {%0,%1,%2,%3};"
        : "+f"(d[0]), "+f"(d[1]), "+f"(d[2]), "+f"(d[3])
        : "r"(a[0]), "r"(a[1]), "r"(a[2]), "r"(a[3]), "r"(b0), "r"(b1));
}
__device__ __forceinline__ unsigned cvt_tf32(float f) {
    unsigned u; asm("cvt.rna.tf32.f32 %0, %1;" : "=r"(u) : "f"(f)); return u;
}
__device__ __forceinline__ float gelu1(float u) {
    return 0.5f * u * (1.f + erff(u * 0.70710678f));
}
__device__ __forceinline__ void fdz(float d[8][4]) {
#pragma unroll
    for (int i = 0; i < 8; i++)
#pragma unroll
        for (int j = 0; j < 4; j++) d[i][j] = 0.f;
}
__device__ __forceinline__ void fdz4(float d[4][4]) {
#pragma unroll
    for (int i = 0; i < 4; i++)
#pragma unroll
        for (int j = 0; j < 4; j++) d[i][j] = 0.f;
}

// Generic tf32 MMA GEMM (N=128): dC += A(64xK, stride sas) @ W(K x 128)
template<bool UA>
__device__ __forceinline__ void mmaG(const float* As, int sas,
    const float* __restrict__ W, long wst, int K,
    float* wsm, float dC[8][4], int tid)
{
    int nk = K >> 3;
    const int lane = tid & 31, wid = tid >> 5;
    const int gq = lane >> 2, tig = lane & 3;
    const int mrow = (wid & 3) * 16, ncol = (wid >> 2) * 64;
#define STG(k0, buf) do{ \
    if (UA){ for (int j = 0; j < 4; j++){ int flat = tid + 256*j; int r_ = flat>>7, col_ = flat&127; \
        cpa4(&(buf)[r_*136 + col_], &W[(size_t)((k0)+r_)*wst + col_]); } } \
    else { int r_ = tid>>5, c4_ = (tid&31)*4; \
        cpa16(&(buf)[r_*136 + c4_], &W[(size_t)((k0)+r_)*wst + c4_]); } \
    cpcommit(); } while(0)
    STG(0, wsm);
    for (int ks = 0; ks < nk; ks++) {
        cpwait0(); __syncthreads();
        if (ks + 1 < nk) STG((ks + 1) * 8, wsm + ((ks + 1) & 1) * 1088);
        const float* wb = wsm + (ks & 1) * 1088;
        unsigned A[4];
        A[0] = cvt_tf32(As[(mrow + gq) * sas + ks * 8 + tig]);
        A[1] = cvt_tf32(As[(mrow + gq + 8) * sas + ks * 8 + tig]);
        A[2] = cvt_tf32(As[(mrow + gq) * sas + ks * 8 + tig + 4]);
        A[3] = cvt_tf32(As[(mrow + gq + 8) * sas + ks * 8 + tig + 4]);
#pragma unroll
        for (int nt = 0; nt < 8; nt++) {
            unsigned b0 = __float_as_uint(wb[tig * 136 + ncol + nt * 8 + gq]);
            unsigned b1 = __float_as_uint(wb[(tig + 4) * 136 + ncol + nt * 8 + gq]);
            mma_tf32(dC[nt], A, b0, b1);
        }
    }
    __syncthreads();
#undef STG
}

// tf32 MMA GEMM (N=64): dC[4][4] += A(64xK, stride sas) @ W(K x 64)
// warp: (wid&3)*16 rows, (wid>>2)*32 cols. Staging 8k x 64 at stride 72 (conflict-free B).
__device__ __forceinline__ void mmaG64(const float* As, int sas,
    const float* __restrict__ W, long wst, int K,
    float* wsm, float dC[4][4], int tid)
{
    int nk = K >> 3;
    const int lane = tid & 31, wid = tid >> 5;
    const int gq = lane >> 2, tig = lane & 3;
    const int mrow = (wid & 3) * 16, ncol = (wid >> 2) * 32;
#define STG64(k0, buf) do{ \
    if (tid < 128){ int r_ = tid >> 4, c4_ = (tid & 15) * 4; \
        cpa16(&(buf)[r_*72 + c4_], &W[(size_t)((k0)+r_)*wst + c4_]); } \
    cpcommit(); } while(0)
    STG64(0, wsm);
    for (int ks = 0; ks < nk; ks++) {
        cpwait0(); __syncthreads();
        if (ks + 1 < nk) STG64((ks + 1) * 8, wsm + ((ks + 1) & 1) * 1088);
        const float* wb = wsm + (ks & 1) * 1088;
        unsigned A[4];
        A[0] = cvt_tf32(As[(mrow + gq) * sas + ks * 8 + tig]);
        A[1] = cvt_tf32(As[(mrow + gq + 8) * sas + ks * 8 + tig]);
        A[2] = cvt_tf32(As[(mrow + gq) * sas + ks * 8 + tig + 4]);
        A[3] = cvt_tf32(As[(mrow + gq + 8) * sas + ks * 8 + tig + 4]);
#pragma unroll
        for (int nt = 0; nt < 4; nt++) {
            unsigned b0 = __float_as_uint(wb[tig * 72 + ncol + nt * 8 + gq]);
            unsigned b1 = __float_as_uint(wb[(tig + 4) * 72 + ncol + nt * 8 + gq]);
            mma_tf32(dC[nt], A, b0, b1);
        }
    }
    __syncthreads();
#undef STG64
}

// epilogue (N=64): buf[row*136 + col] = dC + bias
__device__ __forceinline__ void ep64mma(float dC[4][4], float* buf,
                                        const float* __restrict__ bias, int tid) {
    const int lane = tid & 31, wid = tid >> 5;
    const int gq = lane >> 2, tig = lane & 3;
    const int mrow = (wid & 3) * 16, ncol = (wid >> 2) * 32;
#pragma unroll
    for (int nt = 0; nt < 4; nt++) {
        int c0 = ncol + nt * 8 + 2 * tig;
        float b0 = bias ? bias[c0] : 0.f, b1 = bias ? bias[c0 + 1] : 0.f;
        *(float2*)&buf[(mrow + gq) * 136 + c0]     = make_float2(dC[nt][0] + b0, dC[nt][1] + b1);
        *(float2*)&buf[(mrow + gq + 8) * 136 + c0] = make_float2(dC[nt][2] + b0, dC[nt][3] + b1);
    }
}
// epilogue (N=128): xs += dC + bias
__device__ __forceinline__ void epAddXs(float dC[8][4], float* xs,
                                        const float* __restrict__ bias, int tid) {
    const int lane = tid & 31, wid = tid >> 5;
    const int gq = lane >> 2, tig = lane & 3;
    const int mrow = (wid & 3) * 16, ncol = (wid >> 2) * 64;
#pragma unroll
    for (int nt = 0; nt < 8; nt++) {
        int c0 = ncol + nt * 8 + 2 * tig;
        float b0 = bias[c0], b1 = bias[c0 + 1];
        float2* p0 = (float2*)&xs[(mrow + gq) * 132 + c0];
        float2* p1 = (float2*)&xs[(mrow + gq + 8) * 132 + c0];
        float2 v0 = *p0, v1 = *p1;
        v0.x += dC[nt][0] + b0; v0.y += dC[nt][1] + b1;
        v1.x += dC[nt][2] + b0; v1.y += dC[nt][3] + b1;
        *p0 = v0; *p1 = v1;
    }
}

// ---------- FFMA staging + cores (64-wide; enc/pred/logits only) ----------
__device__ __forceinline__ void st64(const float* __restrict__ W, long wst, int k0,
                                     float* buf, int tid) {
    int r = tid >> 4, cc = tid & 15;
    cpa16(&buf[r * 68 + cc * 4], &W[(size_t)(k0 + r) * wst + cc * 4]);
    cpcommit();
}
__device__ __forceinline__ void inner64(const float* __restrict__ As, int sas, int k0,
                                        const float* wb, U64 c2[][2], int ty, int tx) {
#pragma unroll
    for (int i4 = 0; i4 < 4; i4++) {
        float4 a4[4];
#pragma unroll
        for (int tt = 0; tt < 4; tt++)
            a4[tt] = *(const float4*)&As[(ty * 4 + tt) * sas + k0 + i4 * 4];
#pragma unroll
        for (int ii = 0; ii < 4; ii++) {
            ulonglong2 w = *(const ulonglong2*)&wb[(i4 * 4 + ii) * 68 + tx * 4];
#pragma unroll
            for (int tt = 0; tt < 4; tt++) {
                U64 a = dup2(((const float*)&a4[tt])[ii]);
                f2fma(c2[tt][0], a, w.x);
                f2fma(c2[tt][1], a, w.y);
            }
        }
    }
}
__device__ __forceinline__ void gemm64(const float* __restrict__ As, int sas,
                                       const float* __restrict__ W, long wst, int K,
                                       float* wsm, U64 c2[][2], int ty, int tx, int tid) {
    int nc = K >> 4;
    st64(W, wst, 0, wsm, tid);
    for (int c = 0; c < nc; c++) {
        cpwait0();
        __syncthreads();
        if (c + 1 < nc) st64(W, wst, (c + 1) << 4, wsm + ((c + 1) & 1) * 1088, tid);
        inner64(As, sas, c << 4, wsm + (c & 1) * 1088, c2, ty, tx);
    }
    __syncthreads();
}
__device__ __forceinline__ void gemm64T(const float* __restrict__ As, int sas,
                                        const float* __restrict__ S, int slots, int K,
                                        float* wsm, U64 c2[][2], int ty, int tx, int tid) {
    for (int k0 = 0; k0 < K; k0 += 16) {
        int s = tid & 63, k4 = tid >> 6;
        float4 v = make_float4(0.f, 0.f, 0.f, 0.f);
        if (s < slots) v = *(const float4*)&S[s * 64 + k0 + k4 * 4];
        __syncthreads();
        wsm[(k4 * 4 + 0) * 68 + s] = v.x;
        wsm[(k4 * 4 + 1) * 68 + s] = v.y;
        wsm[(k4 * 4 + 2) * 68 + s] = v.z;
        wsm[(k4 * 4 + 3) * 68 + s] = v.w;
        __syncthreads();
        inner64(As, sas, k0, wsm, c2, ty, tx);
    }
    __syncthreads();
}
__device__ __forceinline__ void fz2(U64* c, int n) {
    for (int i = 0; i < n; i++) c[i] = 0ULL;
}
__device__ __forceinline__ void up2(const U64* c2, float* o) {
    float2 a = unpk(c2[0]), b = unpk(c2[1]);
    o[0] = a.x; o[1] = a.y; o[2] = b.x; o[3] = b.y;
}
template <int SLOTS>
__device__ __forceinline__ void softmax_q(float* buf, int tok, int jq) {
    const int nS = SLOTS / 4;
    float l[nS];
    float m = -1e30f;
#pragma unroll
    for (int i = 0; i < nS; i++) {
        l[i] = buf[tok * 136 + jq * nS + i] * 0.125f;
        m = fmaxf(m, l[i]);
    }
    m = fmaxf(m, __shfl_xor_sync(0xffffffffu, m, 1));
    m = fmaxf(m, __shfl_xor_sync(0xffffffffu, m, 2));
    float s = 0.f;
#pragma unroll
    for (int i = 0; i < nS; i++) { l[i] = expf(l[i] - m); s += l[i]; }
    s += __shfl_xor_sync(0xffffffffu, s, 1);
    s += __shfl_xor_sync(0xffffffffu, s, 2);
    float inv = 1.f / s;
#pragma unroll
    for (int i = 0; i < nS; i++) buf[tok * 136 + jq * nS + i] = l[i] * inv;
}

__global__ void __launch_bounds__(256, 2)
ccg_kernel(
    const float* __restrict__ x_col, const float* __restrict__ pm_state,
    const float* __restrict__ em_state, const float* __restrict__ z_hat_prev,
    const float* __restrict__ ffn_norm_w, const float* __restrict__ ffn_norm_b,
    const float* __restrict__ ffn_up_w, const float* __restrict__ ffn_up_b,
    const float* __restrict__ ffn_down_w, const float* __restrict__ ffn_down_b,
    const float* __restrict__ pm_up_w, const float* __restrict__ pm_up_b,
    const float* __restrict__ pm_down_w, const float* __restrict__ pm_down_b,
    const float* __restrict__ em_up_w, const float* __restrict__ em_up_b,
    const float* __restrict__ em_down_w, const float* __restrict__ em_down_b,
    const float* __restrict__ post_w, const float* __restrict__ post_b,
    const float* __restrict__ enc_w, const float* __restrict__ enc_b,
    const float* __restrict__ pred_w, const float* __restrict__ pred_b,
    const float* __restrict__ gain_w, const float* __restrict__ gain_b,
    float* __restrict__ out)
{
    extern __shared__ float smf[];
    float* xs  = smf;                 // 64 x 132
    float* hs  = xs + 64 * 132;       // 64 x 132
    float* bA  = hs + 64 * 132;       // 64 x 136 (cols 0..67), gelu buf stride 132
    float* bB  = bA + 68;             //             (cols 68..135)
    float* wsm = bA + 64 * 136;       // 2 x 1088 weight staging

    const int tid = threadIdx.x;
    const int ty = tid >> 4, tx = tid & 15;
    const int tok = tid >> 2, jq = tid & 3;
    const int g  = blockIdx.y;
    const int t0 = blockIdx.x * 64;
    const int bs = t0 >> 9;
    const int bidx = g >> 4;

#pragma unroll
    for (int jj = 0; jj < 8; jj++) {
        int flat = tid + 256 * jj;
        int r = flat >> 5, c4 = flat & 31;
        *(float4*)&xs[r * 132 + c4 * 4] =
            *(const float4*)&x_col[((size_t)(t0 + r) * Gn + g) * 128 + c4 * 4];
    }
    __syncthreads();

    // ================= pm memory stage =================
    {
        float dC[4][4]; fdz4(dC);
        mmaG64(xs, 132, pm_up_w + (size_t)g * 8192, 64, 128, wsm, dC, tid);
        ep64mma(dC, bB, pm_up_b + g * 64, tid);
    }
    const float* Spm = pm_state + (size_t)((bs * 8 + bidx) * 16) * 64;
    {
        U64 c2[4][2]; fz2(&c2[0][0], 8);
        gemm64T(bB, 136, Spm, 16, 64, wsm, c2, ty, tx, tid);
        if (tx < 4) {
#pragma unroll
            for (int tt = 0; tt < 4; tt++) {
                float o[4]; up2(c2[tt], o);
#pragma unroll
                for (int j = 0; j < 4; j++) bA[(ty * 4 + tt) * 136 + tx * 4 + j] = o[j];
            }
        }
    }
    __syncthreads();
    softmax_q<16>(bA, tok, jq);
    __syncthreads();
    {
        float dC[4][4]; fdz4(dC);
        mmaG64(bA, 136, Spm, 64, 16, wsm, dC, tid);
        ep64mma(dC, bB, (const float*)0, tid);
    }
    __syncthreads();
    {
        float dC[8][4]; fdz(dC);
        mmaG<false>(bB, 136, pm_down_w + (size_t)g * 8192, 128, 64, wsm, dC, tid);
        epAddXs(dC, xs, pm_down_b + g * 128, tid);
    }
    __syncthreads();

    // ================= em memory stage =================
    {
        float dC[4][4]; fdz4(dC);
        mmaG64(xs, 132, em_up_w + (size_t)g * 8192, 64, 128, wsm, dC, tid);
        ep64mma(dC, bB, em_up_b + g * 64, tid);
    }
    const float* Sem = em_state + (size_t)((bs * 8 + bidx) * 64) * 64;
    {
        U64 c2[4][2]; fz2(&c2[0][0], 8);
        gemm64T(bB, 136, Sem, 64, 64, wsm, c2, ty, tx, tid);
#pragma unroll
        for (int tt = 0; tt < 4; tt++) {
            float o[4]; up2(c2[tt], o);
#pragma unroll
            for (int j = 0; j < 4; j++) bA[(ty * 4 + tt) * 136 + tx * 4 + j] = o[j];
        }
    }
    __syncthreads();
    softmax_q<64>(bA, tok, jq);
    __syncthreads();
    {
        float dC[4][4]; fdz4(dC);
        mmaG64(bA, 136, Sem, 64, 64, wsm, dC, tid);
        ep64mma(dC, bB, (const float*)0, tid);
    }
    __syncthreads();
    {
        float dC[8][4]; fdz(dC);
        mmaG<false>(bB, 136, em_down_w + (size_t)g * 8192, 128, 64, wsm, dC, tid);
        epAddXs(dC, xs, em_down_b + g * 128, tid);
    }
    __syncthreads();

    // ================= enc / delta / surprise (FFMA, precision-critical) =================
    {
        U64 c2[4][2]; fz2(&c2[0][0], 8);
        gemm64(xs, 132, enc_w + (size_t)g * 8192, 64, 128, wsm, c2, ty, tx, tid);
        float sp[4];
#pragma unroll
        for (int tt = 0; tt < 4; tt++) {
            int t = ty * 4 + tt;
            size_t tg = t0 + t;
            float o[4]; up2(c2[tt], o);
            float4 zh4 = *(const float4*)&z_hat_prev[(tg * Gn + g) * 64 + tx * 4];
            float z0 = o[0] + enc_b[g * 64 + tx * 4 + 0];
            float z1 = o[1] + enc_b[g * 64 + tx * 4 + 1];
            float z2 = o[2] + enc_b[g * 64 + tx * 4 + 2];
            float z3 = o[3] + enc_b[g * 64 + tx * 4 + 3];
            bA[t * 136 + tx * 4 + 0] = z0; bA[t * 136 + tx * 4 + 1] = z1;
            bA[t * 136 + tx * 4 + 2] = z2; bA[t * 136 + tx * 4 + 3] = z3;
            float e0 = z0 - zh4.x, e1 = z1 - zh4.y, e2 = z2 - zh4.z, e3 = z3 - zh4.w;
            bB[t * 136 + tx * 4 + 0] = e0; bB[t * 136 + tx * 4 + 1] = e1;
            bB[t * 136 + tx * 4 + 2] = e2; bB[t * 136 + tx * 4 + 3] = e3;
            sp[tt] = e0 * e0 + e1 * e1 + e2 * e2 + e3 * e3;
            *(float4*)&out[O_Z + (tg * Gn + g) * 64 + tx * 4] = make_float4(z0, z1, z2, z3);
        }
#pragma unroll
        for (int tt = 0; tt < 4; tt++) {
            sp[tt] += __shfl_xor_sync(0xffffffffu, sp[tt], 1);
            sp[tt] += __shfl_xor_sync(0xffffffffu, sp[tt], 2);
            sp[tt] += __shfl_xor_sync(0xffffffffu, sp[tt], 4);
            sp[tt] += __shfl_xor_sync(0xffffffffu, sp[tt], 8);
        }
        if (tx == 0) {
#pragma unroll
            for (int tt = 0; tt < 4; tt++) {
                size_t tg = t0 + ty * 4 + tt;
                float s = sqrtf(sp[tt]);
                out[O_SURP + tg * Gn + g] = s;
                out[O_S4 + tg * Gn + g] = s;
                out[O_GATE + tg * Gn + g] = fminf(s, 1.f);
            }
        }
    }
    __syncthreads();

    // ================= gain (delta in bB) via MMA -> hs =================
    {
        float dC[8][4]; fdz(dC);
        mmaG<false>(bB, 136, gain_w + (size_t)g * 8192, 128, 64, wsm, dC, tid);
        const int lane = tid & 31, wid = tid >> 5;
        const int gq = lane >> 2, tig = lane & 3;
        const int mrow = (wid & 3) * 16, ncol = (wid >> 2) * 64;
#pragma unroll
        for (int nt = 0; nt < 8; nt++) {
            int c0 = ncol + nt * 8 + 2 * tig;
            float b0 = gain_b[g * 128 + c0], b1 = gain_b[g * 128 + c0 + 1];
            hs[(mrow + gq) * 132 + c0]     = 1.f + 0.1f * tanhf(dC[nt][0] + b0);
            hs[(mrow + gq) * 132 + c0 + 1] = 1.f + 0.1f * tanhf(dC[nt][1] + b1);
            hs[(mrow + gq + 8) * 132 + c0]     = 1.f + 0.1f * tanhf(dC[nt][2] + b0);
            hs[(mrow + gq + 8) * 132 + c0 + 1] = 1.f + 0.1f * tanhf(dC[nt][3] + b1);
        }
    }

    // ================= z_hat (z in bA, FFMA) =================
    {
        U64 c2[4][2]; fz2(&c2[0][0], 8);
        gemm64(bA, 136, pred_w + (size_t)g * 4096, 64, 64, wsm, c2, ty, tx, tid);
#pragma unroll
        for (int tt = 0; tt < 4; tt++) {
            size_t tg = t0 + ty * 4 + tt;
            float o[4]; up2(c2[tt], o);
            float4 v;
            v.x = o[0] + pred_b[g * 64 + tx * 4 + 0];
            v.y = o[1] + pred_b[g * 64 + tx * 4 + 1];
            v.z = o[2] + pred_b[g * 64 + tx * 4 + 2];
            v.w = o[3] + pred_b[g * 64 + tx * 4 + 3];
            *(float4*)&out[O_ZHAT + (tg * Gn + g) * 64 + tx * 4] = v;
        }
    }
    __syncthreads();

    // ================= layernorm * gain -> hs =================
    {
        float s = 0.f, sq = 0.f;
        float4 xv[8];
#pragma unroll
        for (int u = 0; u < 8; u++) {
            xv[u] = *(const float4*)&xs[tok * 132 + jq * 32 + u * 4];
            s  += xv[u].x + xv[u].y + xv[u].z + xv[u].w;
            sq += xv[u].x * xv[u].x + xv[u].y * xv[u].y + xv[u].z * xv[u].z + xv[u].w * xv[u].w;
        }
        s  += __shfl_xor_sync(0xffffffffu, s, 1);
        s  += __shfl_xor_sync(0xffffffffu, s, 2);
        sq += __shfl_xor_sync(0xffffffffu, sq, 1);
        sq += __shfl_xor_sync(0xffffffffu, sq, 2);
        float mu = s * (1.f / 128.f);
        float rstd = rsqrtf(sq * (1.f / 128.f) - mu * mu + 1e-5f);
#pragma unroll
        for (int u = 0; u < 8; u++) {
            int cb = jq * 32 + u * 4;
            float4 w4 = *(const float4*)&ffn_norm_w[g * 128 + cb];
            float4 b4 = *(const float4*)&ffn_norm_b[g * 128 + cb];
            float4 g4 = *(const float4*)&hs[tok * 132 + cb];
            float4 h4;
            h4.x = ((xv[u].x - mu) * rstd * w4.x + b4.x) * g4.x;
            h4.y = ((xv[u].y - mu) * rstd * w4.y + b4.y) * g4.y;
            h4.z = ((xv[u].z - mu) * rstd * w4.z + b4.z) * g4.z;
            h4.w = ((xv[u].w - mu) * rstd * w4.w + b4.w) * g4.w;
            *(float4*)&hs[tok * 132 + cb] = h4;
        }
    }

    // ================= FFN via tf32 tensor cores =================
    {
        const int wid = tid >> 5, lane = tid & 31;
        const int gq = lane >> 2, tig = lane & 3;
        const int mrow = (wid & 3) * 16;
        const int ncol = (wid >> 2) * 64;
        float* gbuf = bA;

        float dC[8][4]; fdz(dC);

        for (int ch = 0; ch < 4; ch++) {
            float uC[8][4]; fdz(uC);
            {   int r = tid >> 5, c4 = (tid & 31) * 4;
                cpa16(&wsm[r * 136 + c4], &ffn_up_w[(size_t)g * 65536 + (size_t)r * 512 + ch * 128 + c4]);
                cpcommit();
            }
            for (int ks = 0; ks < 16; ks++) {
                cpwait0(); __syncthreads();
                if (ks + 1 < 16) {
                    int r = tid >> 5, c4 = (tid & 31) * 4;
                    cpa16(&wsm[((ks + 1) & 1) * 1088 + r * 136 + c4],
                          &ffn_up_w[(size_t)g * 65536 + (size_t)((ks + 1) * 8 + r) * 512 + ch * 128 + c4]);
                    cpcommit();
                }
                const float* wb = wsm + (ks & 1) * 1088;
                unsigned A[4];
                A[0] = cvt_tf32(hs[(mrow + gq) * 132 + ks * 8 + tig]);
                A[1] = cvt_tf32(hs[(mrow + gq + 8) * 132 + ks * 8 + tig]);
                A[2] = cvt_tf32(hs[(mrow + gq) * 132 + ks * 8 + tig + 4]);
                A[3] = cvt_tf32(hs[(mrow + gq + 8) * 132 + ks * 8 + tig + 4]);
#pragma unroll
                for (int nt = 0; nt < 8; nt++) {
                    unsigned b0 = __float_as_uint(wb[tig * 136 + ncol + nt * 8 + gq]);
                    unsigned b1 = __float_as_uint(wb[(tig + 4) * 136 + ncol + nt * 8 + gq]);
                    mma_tf32(uC[nt], A, b0, b1);
                }
            }
            __syncthreads();
#pragma unroll
            for (int nt = 0; nt < 8; nt++) {
                int c0 = ncol + nt * 8 + 2 * tig;
                float b0 = ffn_up_b[g * 512 + ch * 128 + c0];
                float b1 = ffn_up_b[g * 512 + ch * 128 + c0 + 1];
                gbuf[(mrow + gq) * 132 + c0]     = gelu1(uC[nt][0] + b0);
                gbuf[(mrow + gq) * 132 + c0 + 1] = gelu1(uC[nt][1] + b1);
                gbuf[(mrow + gq + 8) * 132 + c0]     = gelu1(uC[nt][2] + b0);
                gbuf[(mrow + gq + 8) * 132 + c0 + 1] = gelu1(uC[nt][3] + b1);
            }
            {   int r = tid >> 5, c4 = (tid & 31) * 4;
                cpa16(&wsm[r * 136 + c4], &ffn_down_w[(size_t)g * 65536 + (size_t)(ch * 128 + r) * 128 + c4]);
                cpcommit();
            }
            for (int ks = 0; ks < 16; ks++) {
                cpwait0(); __syncthreads();
                if (ks + 1 < 16) {
                    int r = tid >> 5, c4 = (tid & 31) * 4;
                    cpa16(&wsm[((ks + 1) & 1) * 1088 + r * 136 + c4],
                          &ffn_down_w[(size_t)g * 65536 + (size_t)(ch * 128 + (ks + 1) * 8 + r) * 128 + c4]);
                    cpcommit();
                }
                const float* wb = wsm + (ks & 1) * 1088;
                unsigned A[4];
                A[0] = cvt_tf32(gbuf[(mrow + gq) * 132 + ks * 8 + tig]);
                A[1] = cvt_tf32(gbuf[(mrow + gq + 8) * 132 + ks * 8 + tig]);
                A[2] = cvt_tf32(gbuf[(mrow + gq) * 132 + ks * 8 + tig + 4]);
                A[3] = cvt_tf32(gbuf[(mrow + gq + 8) * 132 + ks * 8 + tig + 4]);
#pragma unroll
                for (int nt = 0; nt < 8; nt++) {
                    unsigned b0 = __float_as_uint(wb[tig * 136 + ncol + nt * 8 + gq]);
                    unsigned b1 = __float_as_uint(wb[(tig + 4) * 136 + ncol + nt * 8 + gq]);
                    mma_tf32(dC[nt], A, b0, b1);
                }
            }
            __syncthreads();
        }

#pragma unroll
        for (int nt = 0; nt < 8; nt++) {
            int c0 = ncol + nt * 8 + 2 * tig;
            float b0 = ffn_down_b[g * 128 + c0];
            float b1 = ffn_down_b[g * 128 + c0 + 1];
            int r0 = mrow + gq, r1 = mrow + gq + 8;
            float2 x0 = *(float2*)&xs[r0 * 132 + c0];
            float2 x1 = *(float2*)&xs[r1 * 132 + c0];
            x0.x += dC[nt][0] + b0; x0.y += dC[nt][1] + b1;
            x1.x += dC[nt][2] + b0; x1.y += dC[nt][3] + b1;
            *(float2*)&xs[r0 * 132 + c0] = x0;
            *(float2*)&xs[r1 * 132 + c0] = x1;
            *(float2*)&out[O_XOUT + ((size_t)(t0 + r0) * Gn + g) * 128 + c0] = x0;
            *(float2*)&out[O_XOUT + ((size_t)(t0 + r1) * Gn + g) * 128 + c0] = x1;
        }
    }
    __syncthreads();

    // ================= post projection via MMA (two 128-wide passes) =================
    for (int ph = 0; ph < 2; ph++) {
        float dC[8][4]; fdz(dC);
        mmaG<true>(xs, 132, post_w + (size_t)g * 32896 + ph * 128, 257, 128, wsm, dC, tid);
        long long voff = ph ? O_VC : O_VP;
        long long noff = ph ? O_QN : O_KC;
        {
            const int lane = tid & 31, wid = tid >> 5;
            const int gq = lane >> 2, tig = lane & 3;
            const int mrow = (wid & 3) * 16, ncol = (wid >> 2) * 64;
#pragma unroll
            for (int nt = 0; nt < 8; nt++) {
                int c0 = ncol + nt * 8 + 2 * tig;
                float b0 = post_b[(size_t)g * 257 + ph * 128 + c0];
                float b1 = post_b[(size_t)g * 257 + ph * 128 + c0 + 1];
                float v00 = dC[nt][0] + b0, v01 = dC[nt][1] + b1;
                float v10 = dC[nt][2] + b0, v11 = dC[nt][3] + b1;
                int r0 = mrow + gq, r1 = mrow + gq + 8;
                if (ncol == 0) {
                    *(float2*)&bB[r0 * 136 + c0] = make_float2(v00, v01);
                    *(float2*)&bB[r1 * 136 + c0] = make_float2(v10, v11);
                } else {
                    int cc = c0 - 64;
                    *(float2*)&out[voff + ((size_t)(t0 + r0) * Gn + g) * 64 + cc] = make_float2(v00, v01);
                    *(float2*)&out[voff + ((size_t)(t0 + r1) * Gn + g) * 64 + cc] = make_float2(v10, v11);
                }
            }
        }
        __syncthreads();
        {
            float4 r4[4];
            float ss = 0.f;
#pragma unroll
            for (int u4 = 0; u4 < 4; u4++) {
                r4[u4] = *(const float4*)&bB[tok * 136 + jq * 16 + u4 * 4];
                ss += r4[u4].x * r4[u4].x + r4[u4].y * r4[u4].y
                    + r4[u4].z * r4[u4].z + r4[u4].w * r4[u4].w;
            }
            ss += __shfl_xor_sync(0xffffffffu, ss, 1);
            ss += __shfl_xor_sync(0xffffffffu, ss, 2);
            float inv = 1.f / (sqrtf(ss) + 1e-6f);
            size_t tg = t0 + tok;
#pragma unroll
            for (int u4 = 0; u4 < 4; u4++) {
                float4 v;
                v.x = r4[u4].x * inv; v.y = r4[u4].y * inv;
                v.z = r4[u4].z * inv; v.w = r4[u4].w * inv;
                *(float4*)&out[noff + (tg * Gn + g) * 64 + jq * 16 + u4 * 4] = v;
            }
        }
        __syncthreads();
    }

    // ================= w_nov (proj column 256) =================
    if (tid < 128)
        wsm[tid] = post_w[(size_t)g * 32896 + (size_t)tid * 257 + 256];
    __syncthreads();
    {
        float acc = 0.f;
#pragma unroll
        for (int u = 0; u < 8; u++) {
            float4 xv = *(const float4*)&xs[tok * 132 + jq * 32 + u * 4];
            float4 wv = *(const float4*)&wsm[jq * 32 + u * 4];
            acc += xv.x * wv.x + xv.y * wv.y + xv.z * wv.z + xv.w * wv.w;
        }
        acc += __shfl_xor_sync(0xffffffffu, acc, 1);
        acc += __shfl_xor_sync(0xffffffffu, acc, 2);
        if (jq == 0) {
            size_t tg = t0 + tok;
            float nv = acc + post_b[(size_t)g * 257 + 256];
            out[O_WN + tg * Gn + g] = 1.f / (1.f + expf(-nv));
        }
    }
}

extern "C" void kernel_launch(void* const* d_in, const int* in_sizes, int n_in,
                              void* d_out, int out_size) {
    const float* x_col      = (const float*)d_in[0];
    const float* pm_state   = (const float*)d_in[1];
    const float* em_state   = (const float*)d_in[2];
    const float* z_hat_prev = (const float*)d_in[3];
    const float* ffn_norm_w = (const float*)d_in[4];
    const float* ffn_norm_b = (const float*)d_in[5];
    const float* ffn_up_w   = (const float*)d_in[6];
    const float* ffn_up_b   = (const float*)d_in[7];
    const float* ffn_down_w = (const float*)d_in[8];
    const float* ffn_down_b = (const float*)d_in[9];
    const float* pm_up_w    = (const float*)d_in[10];
    const float* pm_up_b    = (const float*)d_in[11];
    const float* pm_down_w  = (const float*)d_in[12];
    const float* pm_down_b  = (const float*)d_in[13];
    const float* em_up_w    = (const float*)d_in[14];
    const float* em_up_b    = (const float*)d_in[15];
    const float* em_down_w  = (const float*)d_in[16];
    const float* em_down_b  = (const float*)d_in[17];
    const float* post_w     = (const float*)d_in[18];
    const float* post_b     = (const float*)d_in[19];
    const float* enc_w      = (const float*)d_in[20];
    const float* enc_b      = (const float*)d_in[21];
    const float* pred_w     = (const float*)d_in[22];
    const float* pred_b     = (const float*)d_in[23];
    const float* gain_w     = (const float*)d_in[24];
    const float* gain_b     = (const float*)d_in[25];
    float* out = (float*)d_out;

    const int smem = (64 * 132 * 2 + 64 * 136 + 2 * 1088) * 4;  // 111104 B
    cudaFuncSetAttribute(ccg_kernel, cudaFuncAttributeMaxDynamicSharedMemorySize, smem);
    dim3 grid(32, 128);
    ccg_kernel<<<grid, 256, smem>>>(
        x_col, pm_state, em_state, z_hat_prev,
        ffn_norm_w, ffn_norm_b, ffn_up_w, ffn_up_b, ffn_down_w, ffn_down_b,
        pm_up_w, pm_up_b, pm_down_w, pm_down_b,
        em_up_w, em_up_b, em_down_w, em_down_b,
        post_w, post_b, enc_w, enc_b, pred_w, pred_b, gain_w, gain_b,
        out);
}